// round 15
// baseline (speedup 1.0000x reference)
#include <cuda_runtime.h>
#include <cuda_bf16.h>
#include <math.h>
#include <stdint.h>

#define NH 128
#define MAXN 50000
#define MAXE 800000
#define HCOEF 0.1f
#define EPS_BN 1e-5f
#define SSTR 48
#define NBLK 148
#define CGT 1024
#define WSLOT (NH * NH)

// ---------------- device scratch ----------------
__device__ float d_Th[MAXN * NH];
__device__ float d_z[MAXN * NH];
__device__ float d_Xb[4][MAXN * NH];
__device__ float d_vb[4][MAXN * NH];
__device__ float d_Trf[MAXN * NH];
__device__ float d_A1[MAXN * NH];
__device__ float d_A2[MAXN * NH];
__device__ float d_AUb[4][MAXN * NH];
__device__ __nv_bfloat16 d_ZA[MAXN * NH];
__device__ __nv_bfloat16 d_ZB[MAXN * NH];
__device__ __nv_bfloat16 d_WH[17 * WSLOT];
__device__ __nv_bfloat16 d_WL[17 * WSLOT];
__device__ float d_M[WSLOT];
__device__ float d_uvec[NH];
__device__ float d_tvec[NH];
__device__ float d_c0s[1];
__device__ float d_zbias[NH];
__device__ int   d_rowptr[MAXN + 1];
__device__ int   d_cnt[MAXN];
__device__ int   d_bsum[64];
__device__ int   d_cols[MAXE];
__device__ float d_w[MAXE];
__device__ float d_dinv[MAXN];
__device__ float d_scal[4 * SSTR];
__device__ volatile unsigned d_barcnt = 0;
__device__ volatile unsigned d_bargen = 0;

__device__ __forceinline__ void grid_barrier() {
    __syncthreads();
    if (threadIdx.x == 0) {
        unsigned g = d_bargen;
        __threadfence();
        unsigned a = atomicInc((unsigned*)&d_barcnt, NBLK - 1);
        if (a == NBLK - 1) {
            __threadfence();
            d_bargen = g + 1;
        } else {
            while (d_bargen == g) __nanosleep(128);
        }
        __threadfence();
    }
    __syncthreads();
}

// ---------------- helper: combine coefficients from scal ----------------
template <int D>
__device__ __forceinline__ void comb_coeffs(const float* __restrict__ CmAcc, float Ninv,
                                            float* cd) {
#pragma unroll
    for (int k = 0; k < 4; k++) cd[k] = 0.f;
    if (D == 1) { cd[0] = 1.f; return; }
    float Mf[16];
#pragma unroll
    for (int r = 0; r < 4; r++) {
        int mr = (r < 5 - D) ? 0 : (r - (4 - D));
#pragma unroll
        for (int j = 0; j < 4; j++) Mf[r * 4 + j] = __ldg(&CmAcc[mr * 4 + j]) * Ninv;
    }
    float c[4], s = 0.f;
#pragma unroll
    for (int j = 0; j < 4; j++) { c[j] = 0.5f * (Mf[12 + j] + Mf[j * 4 + 3]); s += c[j]; }
    float invs = 1.f / s;
#pragma unroll
    for (int o = 0; o < 4; o++) {
        int mo = (o < 5 - D) ? 0 : (o - (4 - D));
        cd[mo] += c[o] * invs;
    }
}

// ---------------- persistent CSR build ----------------
__global__ __launch_bounds__(CGT, 1) void csr_kernel(
    const int* __restrict__ EI, int E, int N,
    int* __restrict__ cnt, float* __restrict__ dinv, int* __restrict__ bsum,
    int* __restrict__ rowptr, int* __restrict__ cols, float* __restrict__ w) {
    const int tid = blockIdx.x * CGT + threadIdx.x;
    const int nth = NBLK * CGT;
    __shared__ int sh[1024];
    const int nb = (N + 1023) / 1024;

    for (int i = tid; i < N; i += nth) cnt[i] = 0;
    grid_barrier();
    for (int e = tid; e < E; e += nth) {
        int r = EI[e], c = EI[E + e];
        if (r != c) atomicAdd(&cnt[r], 1);
    }
    grid_barrier();
    if (blockIdx.x < nb) {
        int i = blockIdx.x * 1024 + threadIdx.x;
        int x = (i < N) ? cnt[i] : 0;
        if (i < N) dinv[i] = (x > 0) ? rsqrtf((float)x) : 0.f;
        sh[threadIdx.x] = x;
        __syncthreads();
        for (int o = 512; o; o >>= 1) {
            if (threadIdx.x < o) sh[threadIdx.x] += sh[threadIdx.x + o];
            __syncthreads();
        }
        if (threadIdx.x == 0) bsum[blockIdx.x] = sh[0];
    }
    grid_barrier();
    if (blockIdx.x == 0 && threadIdx.x == 0) {
        int run = 0;
        for (int i = 0; i < nb; i++) { int t = bsum[i]; bsum[i] = run; run += t; }
        rowptr[N] = run;
    }
    grid_barrier();
    if (blockIdx.x < nb) {
        int i = blockIdx.x * 1024 + threadIdx.x;
        int x = (i < N) ? cnt[i] : 0;
        sh[threadIdx.x] = x;
        __syncthreads();
        for (int off = 1; off < 1024; off <<= 1) {
            int t = (threadIdx.x >= off) ? sh[threadIdx.x - off] : 0;
            __syncthreads();
            sh[threadIdx.x] += t;
            __syncthreads();
        }
        if (i < N) {
            int excl = sh[threadIdx.x] - x + bsum[blockIdx.x];
            rowptr[i] = excl;
            cnt[i] = excl;
        }
    }
    grid_barrier();
    for (int e = tid; e < E; e += nth) {
        int r = EI[e], c = EI[E + e];
        if (r != c) {
            int pos = atomicAdd(&cnt[r], 1);
            cols[pos] = c;
            w[pos] = -dinv[r] * dinv[c];
        }
    }
}

// ---------------- Gram precompute (+ zero scal/zb) ----------------
__global__ void gram_kernel(const float* __restrict__ Wq, const float* __restrict__ Wk,
                            const float* __restrict__ bq, const float* __restrict__ bk,
                            float* __restrict__ M, float* __restrict__ uv,
                            float* __restrict__ tv, float* __restrict__ c0,
                            float* __restrict__ scal, float* __restrict__ zb) {
    if (blockIdx.x < 64) {
        int idx = blockIdx.x * 256 + threadIdx.x;
        int e = idx >> 7, f = idx & 127;
        float s = 0.f;
        for (int d = 0; d < 128; d++)
            s = fmaf(__ldg(&Wq[d * 128 + e]), __ldg(&Wk[d * 128 + f]), s);
        M[e * 128 + f] = s;
    } else if (blockIdx.x == 64) {
        if (threadIdx.x < 128) {
            int f = threadIdx.x;
            float su = 0.f, st = 0.f;
            for (int d = 0; d < 128; d++) {
                su = fmaf(__ldg(&bq[d]), __ldg(&Wk[d * 128 + f]), su);
                st = fmaf(__ldg(&bk[d]), __ldg(&Wq[d * 128 + f]), st);
            }
            uv[f] = su;
            tv[f] = st;
            if (f == 0) {
                float s = 0.f;
                for (int d = 0; d < 128; d++) s = fmaf(bq[d], bk[d], s);
                *c0 = s;
            }
        }
    } else {
        if (threadIdx.x < 4 * SSTR) scal[threadIdx.x] = 0.f;
        int zi = threadIdx.x - 4 * SSTR;
        if (zi >= 0 && zi < NH) zb[zi] = 0.f;
    }
}

// ---------------- weight pre-conversion ----------------
struct WPtrs { const float* p[17]; };

__global__ void wconv_kernel(WPtrs wp, __nv_bfloat16* WH, __nv_bfloat16* WL) {
    int slot = blockIdx.y;
    int rows = (slot == 16) ? 40 : 128;
    int i = (blockIdx.x * 256 + threadIdx.x) * 4;
    int row = i >> 7;
    __nv_bfloat16* wh = WH + (size_t)slot * WSLOT + i;
    __nv_bfloat16* wl = WL + (size_t)slot * WSLOT + i;
    if (row < rows) {
        float4 v = *(const float4*)(wp.p[slot] + i);
        float a[4] = {v.x, v.y, v.z, v.w};
#pragma unroll
        for (int u = 0; u < 4; u++) {
            __nv_bfloat16 h = __float2bfloat16(a[u]);
            wh[u] = h;
            wl[u] = __float2bfloat16(a[u] - __bfloat162float(h));
        }
    } else {
#pragma unroll
        for (int u = 0; u < 4; u++) { wh[u] = __float2bfloat16(0.f); wl[u] = __float2bfloat16(0.f); }
    }
}

// ---------------- tensor-core GEMM ----------------
__device__ __forceinline__ void mma16816(float* c, const uint32_t* a, const uint32_t* b) {
    asm volatile(
        "mma.sync.aligned.m16n8k16.row.col.f32.bf16.bf16.f32 "
        "{%0,%1,%2,%3}, {%4,%5,%6,%7}, {%8,%9}, {%0,%1,%2,%3};\n"
        : "+f"(c[0]), "+f"(c[1]), "+f"(c[2]), "+f"(c[3])
        : "r"(a[0]), "r"(a[1]), "r"(a[2]), "r"(a[3]), "r"(b[0]), "r"(b[1]));
}
__device__ __forceinline__ void ldsm4(uint32_t* d, uint32_t addr) {
    asm volatile("ldmatrix.sync.aligned.m8n8.x4.shared.b16 {%0,%1,%2,%3}, [%4];"
                 : "=r"(d[0]), "=r"(d[1]), "=r"(d[2]), "=r"(d[3]) : "r"(addr));
}
__device__ __forceinline__ void ldsm2(uint32_t* d, uint32_t addr) {
    asm volatile("ldmatrix.sync.aligned.m8n8.x2.shared.b16 {%0,%1}, [%2];"
                 : "=r"(d[0]), "=r"(d[1]) : "r"(addr));
}
__device__ __forceinline__ void cp_async16(uint32_t dst, const void* src) {
    asm volatile("cp.async.cg.shared.global [%0], [%1], 16;" :: "r"(dst), "l"(src));
}

#define LDW 136
#define GSMEM (4 * 64 * LDW * 2)

__device__ __forceinline__ void split_store(__nv_bfloat16* Ah, __nv_bfloat16* Al,
                                            int base, const float* a) {
    uint32_t hp[2], lp[2];
#pragma unroll
    for (int h2 = 0; h2 < 2; h2++) {
        __nv_bfloat16 h0 = __float2bfloat16(a[h2 * 2]);
        __nv_bfloat16 h1 = __float2bfloat16(a[h2 * 2 + 1]);
        __nv_bfloat16 l0 = __float2bfloat16(a[h2 * 2] - __bfloat162float(h0));
        __nv_bfloat16 l1 = __float2bfloat16(a[h2 * 2 + 1] - __bfloat162float(h1));
        hp[h2] = ((uint32_t)__bfloat16_as_ushort(h1) << 16) | __bfloat16_as_ushort(h0);
        lp[h2] = ((uint32_t)__bfloat16_as_ushort(l1) << 16) | __bfloat16_as_ushort(l0);
    }
    *(uint2*)&Ah[base] = make_uint2(hp[0], hp[1]);
    *(uint2*)&Al[base] = make_uint2(lp[0], lp[1]);
}

// mainloop + epilogue shared by both GEMM variants; A planes already in smem
template <int EPI>
__device__ __forceinline__ void gemm_main(
    uint32_t sAh, uint32_t sAl, uint32_t sWh, uint32_t sWl,
    const float* __restrict__ bsel, float* __restrict__ Csel, int N, int Oc,
    int brow, int colbase,
    const float* __restrict__ bng, const float* __restrict__ bnb,
    const float* __restrict__ bnm, const float* __restrict__ bnv) {
    const int tid = threadIdx.x;
    const int w = tid >> 5, lane = tid & 31;
    const int wm = w >> 2, wn = w & 3;

    float acc[2][2][4];
#pragma unroll
    for (int mt = 0; mt < 2; mt++)
#pragma unroll
        for (int nt = 0; nt < 2; nt++)
#pragma unroll
            for (int u = 0; u < 4; u++) acc[mt][nt][u] = 0.f;

#pragma unroll
    for (int kk = 0; kk < 8; kk++) {
        uint32_t bh[2][2], bl[2][2];
        {
            int r = lane & 7, sel = (lane >> 3) & 1;
            int kcol = kk * 16 + sel * 8;
#pragma unroll
            for (int nt = 0; nt < 2; nt++) {
                int row = wn * 16 + nt * 8 + r;
                uint32_t off = (uint32_t)(row * LDW + kcol) * 2;
                ldsm2(bh[nt], sWh + off);
                ldsm2(bl[nt], sWl + off);
            }
        }
        uint32_t ah[2][4], al[2][4];
        {
            int q = lane >> 3, r = lane & 7;
            int kcol = kk * 16 + (q >> 1) * 8;
#pragma unroll
            for (int mt = 0; mt < 2; mt++) {
                int row = wm * 32 + mt * 16 + (q & 1) * 8 + r;
                uint32_t off = (uint32_t)(row * LDW + kcol) * 2;
                ldsm4(ah[mt], sAh + off);
                ldsm4(al[mt], sAl + off);
            }
        }
#pragma unroll
        for (int mt = 0; mt < 2; mt++)
#pragma unroll
            for (int nt = 0; nt < 2; nt++) {
                mma16816(acc[mt][nt], ah[mt], bh[nt]);
                mma16816(acc[mt][nt], al[mt], bh[nt]);
                mma16816(acc[mt][nt], ah[mt], bl[nt]);
            }
    }

    const int g = lane >> 2, t2 = (lane & 3) * 2;
#pragma unroll
    for (int mt = 0; mt < 2; mt++) {
#pragma unroll
        for (int nt = 0; nt < 2; nt++) {
            int col0 = colbase + wn * 16 + nt * 8 + t2;
#pragma unroll
            for (int half = 0; half < 2; half++) {
                int row = brow + wm * 32 + mt * 16 + g + half * 8;
                if (row >= N) continue;
#pragma unroll
                for (int u = 0; u < 2; u++) {
                    int col = col0 + u;
                    if (col >= Oc) continue;
                    float x = acc[mt][nt][half * 2 + u] + bsel[col];
                    if (EPI) {
                        float s = bng[col] * rsqrtf(bnv[col] + EPS_BN);
                        x = (x - bnm[col]) * s + bnb[col];
                        if (EPI == 1) x = (x > 0.f) ? x : expm1f(x);
                        else x = fmaxf(x, 0.f);
                    }
                    Csel[(size_t)row * Oc + col] = x;
                }
            }
        }
    }
}

__device__ __forceinline__ void load_w_planes(uint32_t sWh, uint32_t sWl,
                                              const __nv_bfloat16* WHp,
                                              const __nv_bfloat16* WLp, int colbase) {
    const int tid = threadIdx.x;
#pragma unroll
    for (int i = 0; i < 4; i++) {
        int ch = i * 256 + tid;
        int row = ch >> 4, cc = ch & 15;
        cp_async16(sWh + (uint32_t)(row * (LDW * 2) + cc * 16),
                   (const char*)WHp + (size_t)(colbase + row) * 256 + cc * 16);
    }
#pragma unroll
    for (int i = 0; i < 4; i++) {
        int ch = i * 256 + tid;
        int row = ch >> 4, cc = ch & 15;
        cp_async16(sWl + (uint32_t)(row * (LDW * 2) + cc * 16),
                   (const char*)WLp + (size_t)(colbase + row) * 256 + cc * 16);
    }
    asm volatile("cp.async.commit_group;");
}

template <int EPI>
__global__ __launch_bounds__(256, 3) void gemm_tc(
    const float* __restrict__ A,
    const __nv_bfloat16* WH1, const __nv_bfloat16* WL1, const float* b1, float* C1,
    const __nv_bfloat16* WH2, const __nv_bfloat16* WL2, const float* b2, float* C2,
    int N, int Oc,
    const float* __restrict__ bng, const float* __restrict__ bnb,
    const float* __restrict__ bnm, const float* __restrict__ bnv) {
    extern __shared__ __align__(16) char smem_raw[];
    __nv_bfloat16* Ah = (__nv_bfloat16*)smem_raw;
    __nv_bfloat16* Al = Ah + 64 * LDW;
    __nv_bfloat16* Wh = Al + 64 * LDW;
    __nv_bfloat16* Wl = Wh + 64 * LDW;
    uint32_t sAh = (uint32_t)__cvta_generic_to_shared(Ah);
    uint32_t sAl = (uint32_t)__cvta_generic_to_shared(Al);
    uint32_t sWh = (uint32_t)__cvta_generic_to_shared(Wh);
    uint32_t sWl = (uint32_t)__cvta_generic_to_shared(Wl);

    int sel = blockIdx.y >> 1, ch = blockIdx.y & 1;
    int colbase = ch * 64;
    int brow = blockIdx.x * 64;
    const int tid = threadIdx.x;

    load_w_planes(sWh, sWl, sel ? WH2 : WH1, sel ? WL2 : WL1, colbase);

#pragma unroll
    for (int i = 0; i < 8; i++) {
        int fl = i * 256 + tid;
        int row = fl >> 5;
        int c4 = (fl & 31) << 2;
        float4 av = make_float4(0.f, 0.f, 0.f, 0.f);
        int gr = brow + row;
        if (gr < N) av = *(const float4*)(A + (size_t)gr * 128 + c4);
        float a[4] = {av.x, av.y, av.z, av.w};
        split_store(Ah, Al, row * LDW + c4, a);
    }
    asm volatile("cp.async.wait_group 0;");
    __syncthreads();
    gemm_main<EPI>(sAh, sAl, sWh, sWl, sel ? b2 : b1, sel ? C2 : C1,
                   N, Oc, brow, colbase, bng, bnb, bnm, bnv);
}

__global__ __launch_bounds__(256, 3) void gemm_tc_b4(
    const float* __restrict__ A, const __nv_bfloat16* WHb, const __nv_bfloat16* WLb,
    const float* __restrict__ bb, float* __restrict__ Cb, size_t Cstride, int N) {
    extern __shared__ __align__(16) char smem_raw[];
    __nv_bfloat16* Ah = (__nv_bfloat16*)smem_raw;
    __nv_bfloat16* Al = Ah + 64 * LDW;
    __nv_bfloat16* Wh = Al + 64 * LDW;
    __nv_bfloat16* Wl = Wh + 64 * LDW;
    uint32_t sAh = (uint32_t)__cvta_generic_to_shared(Ah);
    uint32_t sAl = (uint32_t)__cvta_generic_to_shared(Al);
    uint32_t sWh = (uint32_t)__cvta_generic_to_shared(Wh);
    uint32_t sWl = (uint32_t)__cvta_generic_to_shared(Wl);

    int slot = blockIdx.y >> 1, ch = blockIdx.y & 1;
    int colbase = ch * 64;
    int brow = blockIdx.x * 64;
    const int tid = threadIdx.x;

    load_w_planes(sWh, sWl, WHb + (size_t)slot * WSLOT, WLb + (size_t)slot * WSLOT, colbase);

#pragma unroll
    for (int i = 0; i < 8; i++) {
        int fl = i * 256 + tid;
        int row = fl >> 5;
        int c4 = (fl & 31) << 2;
        float4 av = make_float4(0.f, 0.f, 0.f, 0.f);
        int gr = brow + row;
        if (gr < N) av = *(const float4*)(A + (size_t)gr * 128 + c4);
        float a[4] = {av.x, av.y, av.z, av.w};
        split_store(Ah, Al, row * LDW + c4, a);
    }
    asm volatile("cp.async.wait_group 0;");
    __syncthreads();
    gemm_main<0>(sAh, sAl, sWh, sWl, bb + (size_t)slot * NH, Cb + (size_t)slot * Cstride,
                 N, NH, brow, colbase, 0, 0, 0, 0);
}

// combine-fused GEMM (A = sum cd[k]*da_k), dual-weight via blockIdx.y bit1
template <int D>
__global__ __launch_bounds__(256, 3) void gemm_comb(
    const float* __restrict__ da0, const float* __restrict__ da1,
    const float* __restrict__ da2, const float* __restrict__ da3,
    const float* __restrict__ CmAcc, float Ninv,
    const __nv_bfloat16* WH1, const __nv_bfloat16* WL1, const float* b1, float* C1,
    const __nv_bfloat16* WH2, const __nv_bfloat16* WL2, const float* b2, float* C2,
    int N) {
    extern __shared__ __align__(16) char smem_raw[];
    __nv_bfloat16* Ah = (__nv_bfloat16*)smem_raw;
    __nv_bfloat16* Al = Ah + 64 * LDW;
    __nv_bfloat16* Wh = Al + 64 * LDW;
    __nv_bfloat16* Wl = Wh + 64 * LDW;
    uint32_t sAh = (uint32_t)__cvta_generic_to_shared(Ah);
    uint32_t sAl = (uint32_t)__cvta_generic_to_shared(Al);
    uint32_t sWh = (uint32_t)__cvta_generic_to_shared(Wh);
    uint32_t sWl = (uint32_t)__cvta_generic_to_shared(Wl);

    int sel = blockIdx.y >> 1, ch = blockIdx.y & 1;
    int colbase = ch * 64;
    int brow = blockIdx.x * 64;
    const int tid = threadIdx.x;

    load_w_planes(sWh, sWl, sel ? WH2 : WH1, sel ? WL2 : WL1, colbase);

    float cd[4];
    comb_coeffs<D>(CmAcc, Ninv, cd);
    const float* das[4] = {da0, da1, da2, da3};

#pragma unroll
    for (int i = 0; i < 8; i++) {
        int fl = i * 256 + tid;
        int row = fl >> 5;
        int c4 = (fl & 31) << 2;
        float a[4] = {0.f, 0.f, 0.f, 0.f};
        int gr = brow + row;
        if (gr < N) {
#pragma unroll
            for (int k = 0; k < D; k++) {
                float4 v = *(const float4*)(das[k] + (size_t)gr * 128 + c4);
                a[0] = fmaf(cd[k], v.x, a[0]); a[1] = fmaf(cd[k], v.y, a[1]);
                a[2] = fmaf(cd[k], v.z, a[2]); a[3] = fmaf(cd[k], v.w, a[3]);
            }
        }
        split_store(Ah, Al, row * LDW + c4, a);
    }
    asm volatile("cp.async.wait_group 0;");
    __syncthreads();
    gemm_main<0>(sAh, sAl, sWh, sWl, sel ? b2 : b1, sel ? C2 : C1,
                 N, NH, brow, colbase, 0, 0, 0, 0);
}

// ---------------- attention stats, templated on D distinct slots ----------------
template <int D>
__global__ void attn_kernel(const float* __restrict__ a0, const float* __restrict__ a1,
                            const float* __restrict__ a2, const float* __restrict__ a3,
                            const float* __restrict__ v0, const float* __restrict__ v1,
                            const float* __restrict__ v2, const float* __restrict__ v3,
                            const float* __restrict__ uvp, const float* __restrict__ tvp,
                            const float* __restrict__ c0p,
                            const float* __restrict__ mha, float* __restrict__ Cm, int N) {
    const float scale = 0.08838834764831845f;
    float rfac = fmaxf(mha[0], 0.f);
    float c0 = *c0p;
    int lane = threadIdx.x & 31, wid = threadIdx.x >> 5;
    int gw = blockIdx.x * (blockDim.x >> 5) + wid;
    int tw = gridDim.x * (blockDim.x >> 5);
    const float* as[4] = {a0, a1, a2, a3};
    const float* vs[4] = {v0, v1, v2, v3};
    float4 u4 = *(const float4*)(uvp + lane * 4);
    float4 t4 = *(const float4*)(tvp + lane * 4);
    float acc[16];
#pragma unroll
    for (int m = 0; m < 16; m++) acc[m] = 0.f;
    for (int n = gw; n < N; n += tw) {
        float4 av[D], vv[D];
#pragma unroll
        for (int s = 0; s < D; s++) {
            av[s] = *(const float4*)(as[s] + (size_t)n * NH + lane * 4);
            vv[s] = *(const float4*)(vs[s] + (size_t)n * NH + lane * 4);
        }
        float dd[16], td[4], ud[4];
#pragma unroll
        for (int k = 0; k < D; k++)
#pragma unroll
            for (int l = 0; l < D; l++) {
                float4 a = av[k], b = vv[l];
                float v = a.x * b.x + a.y * b.y + a.z * b.z + a.w * b.w;
#pragma unroll
                for (int o = 16; o; o >>= 1) v += __shfl_xor_sync(0xffffffffu, v, o);
                dd[k * 4 + l] = v;
            }
#pragma unroll
        for (int k = 0; k < D; k++) {
            float4 a = av[k];
            float vt = t4.x * a.x + t4.y * a.y + t4.z * a.z + t4.w * a.w;
            float vu = u4.x * a.x + u4.y * a.y + u4.z * a.z + u4.w * a.w;
#pragma unroll
            for (int o = 16; o; o >>= 1) {
                vt += __shfl_xor_sync(0xffffffffu, vt, o);
                vu += __shfl_xor_sync(0xffffffffu, vu, o);
            }
            td[k] = vt;
            ud[k] = vu;
        }
        if (lane == 0) {
#pragma unroll
            for (int di = 0; di < D; di++) {
                float s4[4];
#pragma unroll
                for (int j = 0; j < 4; j++) {
                    int mj = (j < 5 - D) ? 0 : (j - (4 - D));
                    s4[j] = (dd[di * 4 + mj] + td[di] + ud[mj] + c0) * scale;
                }
                float mx = fmaxf(fmaxf(s4[0], s4[1]), fmaxf(s4[2], s4[3]));
                float e0 = expf(s4[0] - mx), e1 = expf(s4[1] - mx);
                float e2 = expf(s4[2] - mx), e3 = expf(s4[3] - mx);
                float inv = 1.f / (e0 + e1 + e2 + e3);
                acc[di * 4 + 0] += logf(e0 * inv * rfac + 1e-4f);
                acc[di * 4 + 1] += logf(e1 * inv * rfac + 1e-4f);
                acc[di * 4 + 2] += logf(e2 * inv * rfac + 1e-4f);
                acc[di * 4 + 3] += logf(e3 * inv * rfac + 1e-4f);
            }
        }
    }
    __shared__ float sh[8][16];
    if (lane == 0)
#pragma unroll
        for (int m = 0; m < 16; m++) sh[wid][m] = acc[m];
    __syncthreads();
    int nw = blockDim.x >> 5;
    if (threadIdx.x < 16) {
        float s = 0.f;
        for (int w2 = 0; w2 < nw; w2++) s += sh[w2][threadIdx.x];
        atomicAdd(&Cm[threadIdx.x], s);
    }
}

// ---------------- persistent Chebyshev m=2, combine-fused, no register-row-array ----------------
__device__ __forceinline__ float4 bf16row_load(const __nv_bfloat16* p) {
    uint2 zz = *reinterpret_cast<const uint2*>(p);
    __nv_bfloat162 h0 = *reinterpret_cast<__nv_bfloat162*>(&zz.x);
    __nv_bfloat162 h1 = *reinterpret_cast<__nv_bfloat162*>(&zz.y);
    float2 f0 = __bfloat1622float2(h0), f1 = __bfloat1622float2(h1);
    return make_float4(f0.x, f0.y, f1.x, f1.y);
}
__device__ __forceinline__ void bf16row_store(__nv_bfloat16* p, float4 v) {
    __nv_bfloat162 h0 = __floats2bfloat162_rn(v.x, v.y);
    __nv_bfloat162 h1 = __floats2bfloat162_rn(v.z, v.w);
    uint2 zz;
    zz.x = *reinterpret_cast<uint32_t*>(&h0);
    zz.y = *reinterpret_cast<uint32_t*>(&h1);
    *reinterpret_cast<uint2*>(p) = zz;
}

// X = (1+w)*Tr + c1*Z1 + c2*Z2;  Z1 = S*Tr, Z2 = 2*S*Z1 - Tr
template <int D>
__global__ __launch_bounds__(CGT, 1) void cheb_kernel(
    const float* __restrict__ da0, const float* __restrict__ da1,
    const float* __restrict__ da2, const float* __restrict__ da3,
    const float* __restrict__ CmAcc, float Ninv,
    const float* __restrict__ A1, const float* __restrict__ A2,
    const float* __restrict__ AU,
    const float* __restrict__ bng, const float* __restrict__ bnb,
    const float* __restrict__ bnm, const float* __restrict__ bnv,
    const int* __restrict__ rowptr, const int* __restrict__ cols,
    const float* __restrict__ w, const float* __restrict__ Kap,
    float* __restrict__ X, float* __restrict__ Trf,
    __nv_bfloat16* __restrict__ ZA, __nv_bfloat16* __restrict__ ZB, int N) {
    const int tid = blockIdx.x * CGT + threadIdx.x;
    const int lane = threadIdx.x & 31;
    const int gw = tid >> 5;
    const int tw = (NBLK * CGT) >> 5;
    const int cl = lane * 4;

    float4 bg = *(const float4*)(bng + cl), bb = *(const float4*)(bnb + cl);
    float4 bm = *(const float4*)(bnm + cl), bv = *(const float4*)(bnv + cl);
    float4 kk = *(const float4*)(Kap + cl);
    float w1p[4], c1[4], c2[4];
    {
        float kd[4] = {kk.x, kk.y, kk.z, kk.w};
#pragma unroll
        for (int u = 0; u < 4; u++) {
            float k2 = fminf(fmaxf(kd[u], 0.f), 1.f);
            float hk = HCOEF * k2;
            float rt = sqrtf(1.f + 2.f * hk);
            float s = hk / (1.f + hk + rt);
            w1p[u] = 1.f + 1.f / rt;
            c1[u] = -2.f * s / rt;
            c2[u] = -c1[u] * s;
        }
    }
    float bgs[4] = {bg.x * rsqrtf(bv.x + EPS_BN), bg.y * rsqrtf(bv.y + EPS_BN),
                    bg.z * rsqrtf(bv.z + EPS_BN), bg.w * rsqrtf(bv.w + EPS_BN)};

    float cd[4];
    comb_coeffs<D>(CmAcc, Ninv, cd);
    const float* das[4] = {da0, da1, da2, da3};

    // ---- prologue: Tr = elu(bn(T1 + h*dT)); store Trf fp32 + ZA bf16 ----
    for (int r = gw; r < N; r += tw) {
        size_t off = (size_t)r * NH + cl;
        float tt[4] = {0.f, 0.f, 0.f, 0.f};
#pragma unroll
        for (int k = 0; k < D; k++) {
            float4 v = *(const float4*)(das[k] + off);
            tt[0] = fmaf(cd[k], v.x, tt[0]); tt[1] = fmaf(cd[k], v.y, tt[1]);
            tt[2] = fmaf(cd[k], v.z, tt[2]); tt[3] = fmaf(cd[k], v.w, tt[3]);
        }
        float4 a1 = *(const float4*)(A1 + off);
        float4 a2 = *(const float4*)(A2 + off);
        float4 au = *(const float4*)(AU + off);
        float aa1[4] = {a1.x, a1.y, a1.z, a1.w};
        float aa2[4] = {a2.x, a2.y, a2.z, a2.w};
        float aau[4] = {au.x, au.y, au.z, au.w};
        float bbv[4] = {bb.x, bb.y, bb.z, bb.w}, bmv[4] = {bm.x, bm.y, bm.z, bm.w};
        float y[4];
#pragma unroll
        for (int u = 0; u < 4; u++) {
            float d2 = fminf(fmaxf(aa2[u], -1.f), 1.f);
            float yy = tt[u] + HCOEF * (aa1[u] + aau[u] + tt[u] * d2);
            yy = (yy - bmv[u]) * bgs[u] + bbv[u];
            yy = (yy > 0.f) ? yy : expm1f(yy);
            y[u] = yy;
        }
        float4 yv = make_float4(y[0], y[1], y[2], y[3]);
        *(float4*)(Trf + off) = yv;
        bf16row_store(ZA + off, yv);
    }
    grid_barrier();

    // ---- sweep1: Z1 = S*Tr -> ZB ----
    for (int r = gw; r < N; r += tw) {
        int e0 = rowptr[r], e1 = rowptr[r + 1];
        float4 acc = make_float4(0.f, 0.f, 0.f, 0.f);
        for (int e = e0; e < e1; e++) {
            int c = __ldg(&cols[e]);
            float wt = __ldg(&w[e]);
            float4 y = bf16row_load(ZA + (size_t)c * NH + cl);
            acc.x = fmaf(wt, y.x, acc.x); acc.y = fmaf(wt, y.y, acc.y);
            acc.z = fmaf(wt, y.z, acc.z); acc.w = fmaf(wt, y.w, acc.w);
        }
        bf16row_store(ZB + (size_t)r * NH + cl, acc);
    }
    grid_barrier();

    // ---- sweep2: Z2 = 2*S*Z1 - Tr; X = (1+w)*Trf + c1*Z1 + c2*Z2 ----
    for (int r = gw; r < N; r += tw) {
        int e0 = rowptr[r], e1 = rowptr[r + 1];
        float4 acc = make_float4(0.f, 0.f, 0.f, 0.f);
        for (int e = e0; e < e1; e++) {
            int c = __ldg(&cols[e]);
            float wt = __ldg(&w[e]);
            float4 y = bf16row_load(ZB + (size_t)c * NH + cl);
            acc.x = fmaf(wt, y.x, acc.x); acc.y = fmaf(wt, y.y, acc.y);
            acc.z = fmaf(wt, y.z, acc.z); acc.w = fmaf(wt, y.w, acc.w);
        }
        size_t off = (size_t)r * NH + cl;
        float4 trb = bf16row_load(ZA + off);
        float4 z1 = bf16row_load(ZB + off);
        float4 trf = *(const float4*)(Trf + off);
        float4 xv;
        xv.x = w1p[0] * trf.x + c1[0] * z1.x + c2[0] * (2.f * acc.x - trb.x);
        xv.y = w1p[1] * trf.y + c1[1] * z1.y + c2[1] * (2.f * acc.y - trb.y);
        xv.z = w1p[2] * trf.z + c1[2] * z1.z + c2[2] * (2.f * acc.z - trb.z);
        xv.w = w1p[3] * trf.w + c1[3] * z1.w + c2[3] * (2.f * acc.w - trb.w);
        *(float4*)(X + off) = xv;
    }
}

// ---------------- host ----------------
extern "C" void kernel_launch(void* const* d_in, const int* in_sizes, int n_in,
                              void* d_out, int out_size) {
    const float* T      = (const float*)d_in[0];
    const int*   EI     = (const int*)d_in[1];
    const float* KopenW = (const float*)d_in[2];
    const float* Kopenb = (const float*)d_in[3];
    const float* bnOg   = (const float*)d_in[4];
    const float* bnOb   = (const float*)d_in[5];
    const float* bnOm   = (const float*)d_in[6];
    const float* bnOv   = (const float*)d_in[7];
    const float* convW  = (const float*)d_in[8];
    const float* convb  = (const float*)d_in[9];
    const float* bnAg   = (const float*)d_in[10];
    const float* bnAb   = (const float*)d_in[11];
    const float* bnAm   = (const float*)d_in[12];
    const float* bnAv   = (const float*)d_in[13];
    const float* Wq     = (const float*)d_in[14];
    const float* bq     = (const float*)d_in[15];
    const float* Wk     = (const float*)d_in[16];
    const float* bk     = (const float*)d_in[17];
    const float* mha    = (const float*)d_in[18];
    const float* KR1W   = (const float*)d_in[19];
    const float* KR1b   = (const float*)d_in[20];
    const float* KR2W   = (const float*)d_in[21];
    const float* KR2b   = (const float*)d_in[22];
    const float* KRU0W  = (const float*)d_in[23];
    const float* KRU0b  = (const float*)d_in[24];
    const float* bng    = (const float*)d_in[25];
    const float* bnbp   = (const float*)d_in[26];
    const float* bnm    = (const float*)d_in[27];
    const float* bnv    = (const float*)d_in[28];
    const float* Kappa  = (const float*)d_in[29];
    const float* KcloseW= (const float*)d_in[30];
    const float* Kcloseb= (const float*)d_in[31];

    const int N = in_sizes[0] / NH;
    const int E = in_sizes[1] / 2;
    const size_t S = (size_t)MAXN * NH;

    float *Th, *z, *Xb, *vb, *Trf, *A1, *A2, *AUb, *dinvp, *wp, *scal;
    float *Mg, *uvp, *tvp, *c0p, *zb;
    __nv_bfloat16 *WH, *WL, *ZA, *ZB;
    int *rowptr, *cnt, *bsum, *cols;
    cudaGetSymbolAddress((void**)&Th, d_Th);
    cudaGetSymbolAddress((void**)&z, d_z);
    cudaGetSymbolAddress((void**)&Xb, d_Xb);
    cudaGetSymbolAddress((void**)&vb, d_vb);
    cudaGetSymbolAddress((void**)&Trf, d_Trf);
    cudaGetSymbolAddress((void**)&A1, d_A1);
    cudaGetSymbolAddress((void**)&A2, d_A2);
    cudaGetSymbolAddress((void**)&AUb, d_AUb);
    cudaGetSymbolAddress((void**)&ZA, d_ZA);
    cudaGetSymbolAddress((void**)&ZB, d_ZB);
    cudaGetSymbolAddress((void**)&WH, d_WH);
    cudaGetSymbolAddress((void**)&WL, d_WL);
    cudaGetSymbolAddress((void**)&Mg, d_M);
    cudaGetSymbolAddress((void**)&uvp, d_uvec);
    cudaGetSymbolAddress((void**)&tvp, d_tvec);
    cudaGetSymbolAddress((void**)&c0p, d_c0s);
    cudaGetSymbolAddress((void**)&zb, d_zbias);
    cudaGetSymbolAddress((void**)&dinvp, d_dinv);
    cudaGetSymbolAddress((void**)&wp, d_w);
    cudaGetSymbolAddress((void**)&scal, d_scal);
    cudaGetSymbolAddress((void**)&rowptr, d_rowptr);
    cudaGetSymbolAddress((void**)&cnt, d_cnt);
    cudaGetSymbolAddress((void**)&bsum, d_bsum);
    cudaGetSymbolAddress((void**)&cols, d_cols);

    static bool attr_done = false;
    if (!attr_done) {
        cudaFuncSetAttribute(gemm_tc<0>, cudaFuncAttributeMaxDynamicSharedMemorySize, GSMEM);
        cudaFuncSetAttribute(gemm_tc<1>, cudaFuncAttributeMaxDynamicSharedMemorySize, GSMEM);
        cudaFuncSetAttribute(gemm_tc<2>, cudaFuncAttributeMaxDynamicSharedMemorySize, GSMEM);
        cudaFuncSetAttribute(gemm_tc_b4, cudaFuncAttributeMaxDynamicSharedMemorySize, GSMEM);
        cudaFuncSetAttribute(gemm_comb<2>, cudaFuncAttributeMaxDynamicSharedMemorySize, GSMEM);
        cudaFuncSetAttribute(gemm_comb<3>, cudaFuncAttributeMaxDynamicSharedMemorySize, GSMEM);
        cudaFuncSetAttribute(gemm_comb<4>, cudaFuncAttributeMaxDynamicSharedMemorySize, GSMEM);
        attr_done = true;
    }

    const int GBX = (N + 63) / 64;
    dim3 gs1(GBX, 2), gs2(GBX, 4), gb4(GBX, 8), gcl(GBX, 1);
    const float Ninv = 1.0f / (float)N;

    gram_kernel<<<66, 256>>>(Wq, Wk, bq, bk, Mg, uvp, tvp, c0p, scal, zb);

    WPtrs wpt;
    wpt.p[0] = KopenW; wpt.p[1] = convW; wpt.p[2] = Mg; wpt.p[3] = Mg;
    for (int j = 0; j < 4; j++) {
        wpt.p[4 + j] = KR1W + (size_t)j * WSLOT;
        wpt.p[8 + j] = KR2W + (size_t)j * WSLOT;
        wpt.p[12 + j] = KRU0W + (size_t)j * WSLOT;
    }
    wpt.p[16] = KcloseW;
    wconv_kernel<<<dim3(16, 17), 256>>>(wpt, WH, WL);

    csr_kernel<<<NBLK, CGT>>>(EI, E, N, cnt, dinvp, bsum, rowptr, cols, wp);

    gemm_tc<1><<<gs1, 256, GSMEM>>>(T, WH, WL, Kopenb, Th, WH, WL, Kopenb, Th, N, NH,
                                    bnOg, bnOb, bnOm, bnOv);
    gemm_tc<2><<<gs1, 256, GSMEM>>>(Th, WH + 1 * WSLOT, WL + 1 * WSLOT, convb, z,
                                    WH + 1 * WSLOT, WL + 1 * WSLOT, convb, z, N, NH,
                                    bnAg, bnAb, bnAm, bnAv);
    gemm_tc<0><<<gs1, 256, GSMEM>>>(z, WH + 2 * WSLOT, WL + 2 * WSLOT, zb, vb,
                                    WH + 2 * WSLOT, WL + 2 * WSLOT, zb, vb, N, NH, 0, 0, 0, 0);
    gemm_tc_b4<<<gb4, 256, GSMEM>>>(Th, WH + 12 * WSLOT, WL + 12 * WSLOT, KRU0b, AUb, S, N);

    for (int jj = 0; jj < 4; jj++) {
        const float *da[4] = {z, z, z, z};
        for (int m = 0; m < jj; m++) da[m + 1] = Xb + m * S;
        float* sl = scal + jj * SSTR;

        if (jj == 0) {
            // T1 == z exactly (uniform softmax)
            gemm_tc<0><<<gs2, 256, GSMEM>>>(z,
                                            WH + 4 * WSLOT, WL + 4 * WSLOT, KR1b, A1,
                                            WH + 8 * WSLOT, WL + 8 * WSLOT, KR2b, A2,
                                            N, NH, 0, 0, 0, 0);
            cheb_kernel<1><<<NBLK, CGT>>>(z, z, z, z, sl, Ninv, A1, A2, AUb,
                                          bng, bnbp, bnm, bnv, rowptr, cols, wp,
                                          Kappa, Xb, Trf, ZA, ZB, N);
        } else {
            gemm_tc<0><<<gs1, 256, GSMEM>>>(Xb + (jj - 1) * S,
                                            WH + 2 * WSLOT, WL + 2 * WSLOT, zb, vb + jj * S,
                                            WH + 2 * WSLOT, WL + 2 * WSLOT, zb, vb + jj * S,
                                            N, NH, 0, 0, 0, 0);
            const float *dv[4] = {vb, vb, vb, vb};
            for (int m = 0; m < jj; m++) dv[m + 1] = vb + (m + 1) * S;

            const __nv_bfloat16* wh1 = WH + (4 + jj) * WSLOT;
            const __nv_bfloat16* wl1 = WL + (4 + jj) * WSLOT;
            const __nv_bfloat16* wh2 = WH + (8 + jj) * WSLOT;
            const __nv_bfloat16* wl2 = WL + (8 + jj) * WSLOT;
            float* X = Xb + jj * S;

            if (jj == 1) {
                attn_kernel<2><<<400, 256>>>(da[0], da[1], da[2], da[3],
                                             dv[0], dv[1], dv[2], dv[3],
                                             uvp, tvp, c0p, mha, sl, N);
                gemm_comb<2><<<gs2, 256, GSMEM>>>(da[0], da[1], da[2], da[3], sl, Ninv,
                                                  wh1, wl1, KR1b + jj * NH, A1,
                                                  wh2, wl2, KR2b + jj * NH, A2, N);
                cheb_kernel<2><<<NBLK, CGT>>>(da[0], da[1], da[2], da[3], sl, Ninv,
                                              A1, A2, AUb + jj * S,
                                              bng + jj * NH, bnbp + jj * NH,
                                              bnm + jj * NH, bnv + jj * NH,
                                              rowptr, cols, wp, Kappa + jj * NH,
                                              X, Trf, ZA, ZB, N);
            } else if (jj == 2) {
                attn_kernel<3><<<400, 256>>>(da[0], da[1], da[2], da[3],
                                             dv[0], dv[1], dv[2], dv[3],
                                             uvp, tvp, c0p, mha, sl, N);
                gemm_comb<3><<<gs2, 256, GSMEM>>>(da[0], da[1], da[2], da[3], sl, Ninv,
                                                  wh1, wl1, KR1b + jj * NH, A1,
                                                  wh2, wl2, KR2b + jj * NH, A2, N);
                cheb_kernel<3><<<NBLK, CGT>>>(da[0], da[1], da[2], da[3], sl, Ninv,
                                              A1, A2, AUb + jj * S,
                                              bng + jj * NH, bnbp + jj * NH,
                                              bnm + jj * NH, bnv + jj * NH,
                                              rowptr, cols, wp, Kappa + jj * NH,
                                              X, Trf, ZA, ZB, N);
            } else {
                attn_kernel<4><<<400, 256>>>(da[0], da[1], da[2], da[3],
                                             dv[0], dv[1], dv[2], dv[3],
                                             uvp, tvp, c0p, mha, sl, N);
                gemm_comb<4><<<gs2, 256, GSMEM>>>(da[0], da[1], da[2], da[3], sl, Ninv,
                                                  wh1, wl1, KR1b + jj * NH, A1,
                                                  wh2, wl2, KR2b + jj * NH, A2, N);
                cheb_kernel<4><<<NBLK, CGT>>>(da[0], da[1], da[2], da[3], sl, Ninv,
                                              A1, A2, AUb + jj * S,
                                              bng + jj * NH, bnbp + jj * NH,
                                              bnm + jj * NH, bnv + jj * NH,
                                              rowptr, cols, wp, Kappa + jj * NH,
                                              X, Trf, ZA, ZB, N);
            }
        }
    }
    gemm_tc<0><<<gcl, 256, GSMEM>>>(Xb + 3 * S, WH + 16 * WSLOT, WL + 16 * WSLOT, Kcloseb,
                                    (float*)d_out, WH + 16 * WSLOT, WL + 16 * WSLOT, Kcloseb,
                                    (float*)d_out, N, 40, 0, 0, 0, 0);
}

// round 16
// speedup vs baseline: 1.0643x; 1.0643x over previous
#include <cuda_runtime.h>
#include <cuda_bf16.h>
#include <math.h>
#include <stdint.h>

#define NH 128
#define MAXN 50000
#define MAXE 800000
#define HCOEF 0.1f
#define EPS_BN 1e-5f
#define SSTR 48
#define NBLK 148
#define CGT 1024
#define CHEB_M 2
#define WSLOT (NH * NH)
#define MAXR 11

// ---------------- device scratch ----------------
__device__ float d_Th[MAXN * NH];
__device__ float d_z[MAXN * NH];
__device__ float d_Xb[4][MAXN * NH];
__device__ float d_vb[4][MAXN * NH];
__device__ float d_T1[MAXN * NH];
__device__ float d_A1[MAXN * NH];
__device__ float d_A2[MAXN * NH];
__device__ float d_AUb[4][MAXN * NH];
__device__ __nv_bfloat16 d_ZA[MAXN * NH];
__device__ __nv_bfloat16 d_ZB[MAXN * NH];
__device__ __nv_bfloat16 d_WH[17 * WSLOT];
__device__ __nv_bfloat16 d_WL[17 * WSLOT];
__device__ float d_M[WSLOT];
__device__ float d_uvec[NH];
__device__ float d_tvec[NH];
__device__ float d_c0s[1];
__device__ float d_zbias[NH];
__device__ int   d_rowptr[MAXN + 1];
__device__ int   d_cnt[MAXN];
__device__ int   d_bsum[64];
__device__ int   d_cols[MAXE];
__device__ float d_w[MAXE];
__device__ float d_dinv[MAXN];
__device__ float d_scal[4 * SSTR];
__device__ volatile unsigned d_barcnt = 0;
__device__ volatile unsigned d_bargen = 0;

__device__ __forceinline__ void grid_barrier() {
    __syncthreads();
    if (threadIdx.x == 0) {
        unsigned g = d_bargen;
        __threadfence();
        unsigned a = atomicInc((unsigned*)&d_barcnt, NBLK - 1);
        if (a == NBLK - 1) {
            __threadfence();
            d_bargen = g + 1;
        } else {
            while (d_bargen == g) __nanosleep(128);
        }
        __threadfence();
    }
    __syncthreads();
}

// ---------------- persistent CSR build ----------------
__global__ __launch_bounds__(CGT, 1) void csr_kernel(
    const int* __restrict__ EI, int E, int N,
    int* __restrict__ cnt, float* __restrict__ dinv, int* __restrict__ bsum,
    int* __restrict__ rowptr, int* __restrict__ cols, float* __restrict__ w) {
    const int tid = blockIdx.x * CGT + threadIdx.x;
    const int nth = NBLK * CGT;
    __shared__ int sh[1024];
    const int nb = (N + 1023) / 1024;

    for (int i = tid; i < N; i += nth) cnt[i] = 0;
    grid_barrier();
    for (int e = tid; e < E; e += nth) {
        int r = EI[e], c = EI[E + e];
        if (r != c) atomicAdd(&cnt[r], 1);
    }
    grid_barrier();
    if (blockIdx.x < nb) {
        int i = blockIdx.x * 1024 + threadIdx.x;
        int x = (i < N) ? cnt[i] : 0;
        if (i < N) dinv[i] = (x > 0) ? rsqrtf((float)x) : 0.f;
        sh[threadIdx.x] = x;
        __syncthreads();
        for (int o = 512; o; o >>= 1) {
            if (threadIdx.x < o) sh[threadIdx.x] += sh[threadIdx.x + o];
            __syncthreads();
        }
        if (threadIdx.x == 0) bsum[blockIdx.x] = sh[0];
    }
    grid_barrier();
    if (blockIdx.x == 0 && threadIdx.x == 0) {
        int run = 0;
        for (int i = 0; i < nb; i++) { int t = bsum[i]; bsum[i] = run; run += t; }
        rowptr[N] = run;
    }
    grid_barrier();
    if (blockIdx.x < nb) {
        int i = blockIdx.x * 1024 + threadIdx.x;
        int x = (i < N) ? cnt[i] : 0;
        sh[threadIdx.x] = x;
        __syncthreads();
        for (int off = 1; off < 1024; off <<= 1) {
            int t = (threadIdx.x >= off) ? sh[threadIdx.x - off] : 0;
            __syncthreads();
            sh[threadIdx.x] += t;
            __syncthreads();
        }
        if (i < N) {
            int excl = sh[threadIdx.x] - x + bsum[blockIdx.x];
            rowptr[i] = excl;
            cnt[i] = excl;
        }
    }
    grid_barrier();
    for (int e = tid; e < E; e += nth) {
        int r = EI[e], c = EI[E + e];
        if (r != c) {
            int pos = atomicAdd(&cnt[r], 1);
            cols[pos] = c;
            w[pos] = -dinv[r] * dinv[c];
        }
    }
}

// ---------------- Gram precompute (+ zero scal/zb) ----------------
__global__ void gram_kernel(const float* __restrict__ Wq, const float* __restrict__ Wk,
                            const float* __restrict__ bq, const float* __restrict__ bk,
                            float* __restrict__ M, float* __restrict__ uv,
                            float* __restrict__ tv, float* __restrict__ c0,
                            float* __restrict__ scal, float* __restrict__ zb) {
    if (blockIdx.x < 64) {
        int idx = blockIdx.x * 256 + threadIdx.x;
        int e = idx >> 7, f = idx & 127;
        float s = 0.f;
        for (int d = 0; d < 128; d++)
            s = fmaf(__ldg(&Wq[d * 128 + e]), __ldg(&Wk[d * 128 + f]), s);
        M[e * 128 + f] = s;
    } else if (blockIdx.x == 64) {
        if (threadIdx.x < 128) {
            int f = threadIdx.x;
            float su = 0.f, st = 0.f;
            for (int d = 0; d < 128; d++) {
                su = fmaf(__ldg(&bq[d]), __ldg(&Wk[d * 128 + f]), su);
                st = fmaf(__ldg(&bk[d]), __ldg(&Wq[d * 128 + f]), st);
            }
            uv[f] = su;
            tv[f] = st;
            if (f == 0) {
                float s = 0.f;
                for (int d = 0; d < 128; d++) s = fmaf(bq[d], bk[d], s);
                *c0 = s;
            }
        }
    } else {
        if (threadIdx.x < 4 * SSTR) scal[threadIdx.x] = 0.f;
        int zi = threadIdx.x - 4 * SSTR;
        if (zi >= 0 && zi < NH) zb[zi] = 0.f;
    }
}

// ---------------- weight pre-conversion ----------------
struct WPtrs { const float* p[17]; };

__global__ void wconv_kernel(WPtrs wp, __nv_bfloat16* WH, __nv_bfloat16* WL) {
    int slot = blockIdx.y;
    int rows = (slot == 16) ? 40 : 128;
    int i = (blockIdx.x * 256 + threadIdx.x) * 4;
    int row = i >> 7;
    __nv_bfloat16* wh = WH + (size_t)slot * WSLOT + i;
    __nv_bfloat16* wl = WL + (size_t)slot * WSLOT + i;
    if (row < rows) {
        float4 v = *(const float4*)(wp.p[slot] + i);
        float a[4] = {v.x, v.y, v.z, v.w};
#pragma unroll
        for (int u = 0; u < 4; u++) {
            __nv_bfloat16 h = __float2bfloat16(a[u]);
            wh[u] = h;
            wl[u] = __float2bfloat16(a[u] - __bfloat162float(h));
        }
    } else {
#pragma unroll
        for (int u = 0; u < 4; u++) { wh[u] = __float2bfloat16(0.f); wl[u] = __float2bfloat16(0.f); }
    }
}

// ---------------- tensor-core GEMM: 64x64 tiles, fused 3-term split, 3 CTA/SM ----------------
__device__ __forceinline__ void mma16816(float* c, const uint32_t* a, const uint32_t* b) {
    asm volatile(
        "mma.sync.aligned.m16n8k16.row.col.f32.bf16.bf16.f32 "
        "{%0,%1,%2,%3}, {%4,%5,%6,%7}, {%8,%9}, {%0,%1,%2,%3};\n"
        : "+f"(c[0]), "+f"(c[1]), "+f"(c[2]), "+f"(c[3])
        : "r"(a[0]), "r"(a[1]), "r"(a[2]), "r"(a[3]), "r"(b[0]), "r"(b[1]));
}
__device__ __forceinline__ void ldsm4(uint32_t* d, uint32_t addr) {
    asm volatile("ldmatrix.sync.aligned.m8n8.x4.shared.b16 {%0,%1,%2,%3}, [%4];"
                 : "=r"(d[0]), "=r"(d[1]), "=r"(d[2]), "=r"(d[3]) : "r"(addr));
}
__device__ __forceinline__ void ldsm2(uint32_t* d, uint32_t addr) {
    asm volatile("ldmatrix.sync.aligned.m8n8.x2.shared.b16 {%0,%1}, [%2];"
                 : "=r"(d[0]), "=r"(d[1]) : "r"(addr));
}
__device__ __forceinline__ void cp_async16(uint32_t dst, const void* src) {
    asm volatile("cp.async.cg.shared.global [%0], [%1], 16;" :: "r"(dst), "l"(src));
}

#define LDW 136
#define GSMEM (4 * 64 * LDW * 2)

template <int EPI>
__device__ __forceinline__ void gemm_body(
    const float* __restrict__ A,
    const __nv_bfloat16* __restrict__ WHp, const __nv_bfloat16* __restrict__ WLp,
    const float* __restrict__ bsel, float* __restrict__ Csel, int N, int Oc, int colbase,
    const float* __restrict__ bng, const float* __restrict__ bnb,
    const float* __restrict__ bnm, const float* __restrict__ bnv) {
    extern __shared__ __align__(16) char smem_raw[];
    __nv_bfloat16* Ah = (__nv_bfloat16*)smem_raw;
    __nv_bfloat16* Al = Ah + 64 * LDW;
    __nv_bfloat16* Wh = Al + 64 * LDW;
    __nv_bfloat16* Wl = Wh + 64 * LDW;

    const int tid = threadIdx.x;
    const int brow = blockIdx.x * 64;

    uint32_t sAh = (uint32_t)__cvta_generic_to_shared(Ah);
    uint32_t sAl = (uint32_t)__cvta_generic_to_shared(Al);
    uint32_t sWh = (uint32_t)__cvta_generic_to_shared(Wh);
    uint32_t sWl = (uint32_t)__cvta_generic_to_shared(Wl);

#pragma unroll
    for (int i = 0; i < 4; i++) {
        int ch = i * 256 + tid;
        int row = ch >> 4, cc = ch & 15;
        cp_async16(sWh + (uint32_t)(row * (LDW * 2) + cc * 16),
                   (const char*)WHp + (size_t)(colbase + row) * 256 + cc * 16);
    }
#pragma unroll
    for (int i = 0; i < 4; i++) {
        int ch = i * 256 + tid;
        int row = ch >> 4, cc = ch & 15;
        cp_async16(sWl + (uint32_t)(row * (LDW * 2) + cc * 16),
                   (const char*)WLp + (size_t)(colbase + row) * 256 + cc * 16);
    }
    asm volatile("cp.async.commit_group;");

#pragma unroll
    for (int i = 0; i < 8; i++) {
        int fl = i * 256 + tid;
        int row = fl >> 5;
        int c4 = (fl & 31) << 2;
        float4 av = make_float4(0.f, 0.f, 0.f, 0.f);
        int gr = brow + row;
        if (gr < N) av = *(const float4*)(A + (size_t)gr * 128 + c4);
        float a[4] = {av.x, av.y, av.z, av.w};
        uint32_t hp[2], lp[2];
#pragma unroll
        for (int h2 = 0; h2 < 2; h2++) {
            __nv_bfloat16 h0 = __float2bfloat16(a[h2 * 2]);
            __nv_bfloat16 h1 = __float2bfloat16(a[h2 * 2 + 1]);
            __nv_bfloat16 l0 = __float2bfloat16(a[h2 * 2] - __bfloat162float(h0));
            __nv_bfloat16 l1 = __float2bfloat16(a[h2 * 2 + 1] - __bfloat162float(h1));
            hp[h2] = ((uint32_t)__bfloat16_as_ushort(h1) << 16) | __bfloat16_as_ushort(h0);
            lp[h2] = ((uint32_t)__bfloat16_as_ushort(l1) << 16) | __bfloat16_as_ushort(l0);
        }
        int base = row * LDW + c4;
        *(uint2*)&Ah[base] = make_uint2(hp[0], hp[1]);
        *(uint2*)&Al[base] = make_uint2(lp[0], lp[1]);
    }
    asm volatile("cp.async.wait_group 0;");
    __syncthreads();

    const int w = tid >> 5, lane = tid & 31;
    const int wm = w >> 2, wn = w & 3;

    float acc[2][2][4];
#pragma unroll
    for (int mt = 0; mt < 2; mt++)
#pragma unroll
        for (int nt = 0; nt < 2; nt++)
#pragma unroll
            for (int u = 0; u < 4; u++) acc[mt][nt][u] = 0.f;

#pragma unroll
    for (int kk = 0; kk < 8; kk++) {
        uint32_t bh[2][2], bl[2][2];
        {
            int r = lane & 7, sel = (lane >> 3) & 1;
            int kcol = kk * 16 + sel * 8;
#pragma unroll
            for (int nt = 0; nt < 2; nt++) {
                int row = wn * 16 + nt * 8 + r;
                uint32_t off = (uint32_t)(row * LDW + kcol) * 2;
                ldsm2(bh[nt], sWh + off);
                ldsm2(bl[nt], sWl + off);
            }
        }
        uint32_t ah[2][4], al[2][4];
        {
            int q = lane >> 3, r = lane & 7;
            int kcol = kk * 16 + (q >> 1) * 8;
#pragma unroll
            for (int mt = 0; mt < 2; mt++) {
                int row = wm * 32 + mt * 16 + (q & 1) * 8 + r;
                uint32_t off = (uint32_t)(row * LDW + kcol) * 2;
                ldsm4(ah[mt], sAh + off);
                ldsm4(al[mt], sAl + off);
            }
        }
#pragma unroll
        for (int mt = 0; mt < 2; mt++)
#pragma unroll
            for (int nt = 0; nt < 2; nt++) {
                mma16816(acc[mt][nt], ah[mt], bh[nt]);
                mma16816(acc[mt][nt], al[mt], bh[nt]);
                mma16816(acc[mt][nt], ah[mt], bl[nt]);
            }
    }

    const int g = lane >> 2, t2 = (lane & 3) * 2;
#pragma unroll
    for (int mt = 0; mt < 2; mt++) {
#pragma unroll
        for (int nt = 0; nt < 2; nt++) {
            int col0 = colbase + wn * 16 + nt * 8 + t2;
#pragma unroll
            for (int half = 0; half < 2; half++) {
                int row = brow + wm * 32 + mt * 16 + g + half * 8;
                if (row >= N) continue;
#pragma unroll
                for (int u = 0; u < 2; u++) {
                    int col = col0 + u;
                    if (col >= Oc) continue;
                    float x = acc[mt][nt][half * 2 + u] + bsel[col];
                    if (EPI) {
                        float s = bng[col] * rsqrtf(bnv[col] + EPS_BN);
                        x = (x - bnm[col]) * s + bnb[col];
                        if (EPI == 1) x = (x > 0.f) ? x : expm1f(x);
                        else x = fmaxf(x, 0.f);
                    }
                    Csel[(size_t)row * Oc + col] = x;
                }
            }
        }
    }
}

template <int EPI>
__global__ __launch_bounds__(256, 3) void gemm_tc(
    const float* __restrict__ A,
    const __nv_bfloat16* WH1, const __nv_bfloat16* WL1, const float* b1, float* C1,
    const __nv_bfloat16* WH2, const __nv_bfloat16* WL2, const float* b2, float* C2,
    int N, int Oc,
    const float* __restrict__ bng, const float* __restrict__ bnb,
    const float* __restrict__ bnm, const float* __restrict__ bnv) {
    int sel = blockIdx.y >> 1, ch = blockIdx.y & 1;
    gemm_body<EPI>(A, sel ? WH2 : WH1, sel ? WL2 : WL1, sel ? b2 : b1,
                   sel ? C2 : C1, N, Oc, ch * 64, bng, bnb, bnm, bnv);
}

__global__ __launch_bounds__(256, 3) void gemm_tc_b4(
    const float* __restrict__ A, const __nv_bfloat16* WHb, const __nv_bfloat16* WLb,
    const float* __restrict__ bb, float* __restrict__ Cb, size_t Cstride, int N) {
    int slot = blockIdx.y >> 1, ch = blockIdx.y & 1;
    gemm_body<0>(A, WHb + (size_t)slot * WSLOT, WLb + (size_t)slot * WSLOT,
                 bb + (size_t)slot * NH, Cb + (size_t)slot * Cstride,
                 N, NH, ch * 64, 0, 0, 0, 0);
}

// ---------------- attention stats, templated on D distinct slots ----------------
template <int D>
__global__ void attn_kernel(const float* __restrict__ a0, const float* __restrict__ a1,
                            const float* __restrict__ a2, const float* __restrict__ a3,
                            const float* __restrict__ v0, const float* __restrict__ v1,
                            const float* __restrict__ v2, const float* __restrict__ v3,
                            const float* __restrict__ uvp, const float* __restrict__ tvp,
                            const float* __restrict__ c0p,
                            const float* __restrict__ mha, float* __restrict__ Cm, int N) {
    const float scale = 0.08838834764831845f;
    float rfac = fmaxf(mha[0], 0.f);
    float c0 = *c0p;
    int lane = threadIdx.x & 31, wid = threadIdx.x >> 5;
    int gw = blockIdx.x * (blockDim.x >> 5) + wid;
    int tw = gridDim.x * (blockDim.x >> 5);
    const float* as[4] = {a0, a1, a2, a3};
    const float* vs[4] = {v0, v1, v2, v3};
    float4 u4 = *(const float4*)(uvp + lane * 4);
    float4 t4 = *(const float4*)(tvp + lane * 4);
    float acc[16];
#pragma unroll
    for (int m = 0; m < 16; m++) acc[m] = 0.f;
    for (int n = gw; n < N; n += tw) {
        float4 av[D], vv[D];
#pragma unroll
        for (int s = 0; s < D; s++) {
            av[s] = *(const float4*)(as[s] + (size_t)n * NH + lane * 4);
            vv[s] = *(const float4*)(vs[s] + (size_t)n * NH + lane * 4);
        }
        float dd[16], td[4], ud[4];
#pragma unroll
        for (int k = 0; k < D; k++)
#pragma unroll
            for (int l = 0; l < D; l++) {
                float4 a = av[k], b = vv[l];
                float v = a.x * b.x + a.y * b.y + a.z * b.z + a.w * b.w;
#pragma unroll
                for (int o = 16; o; o >>= 1) v += __shfl_xor_sync(0xffffffffu, v, o);
                dd[k * 4 + l] = v;
            }
#pragma unroll
        for (int k = 0; k < D; k++) {
            float4 a = av[k];
            float vt = t4.x * a.x + t4.y * a.y + t4.z * a.z + t4.w * a.w;
            float vu = u4.x * a.x + u4.y * a.y + u4.z * a.z + u4.w * a.w;
#pragma unroll
            for (int o = 16; o; o >>= 1) {
                vt += __shfl_xor_sync(0xffffffffu, vt, o);
                vu += __shfl_xor_sync(0xffffffffu, vu, o);
            }
            td[k] = vt;
            ud[k] = vu;
        }
        if (lane == 0) {
#pragma unroll
            for (int di = 0; di < D; di++) {
                float s4[4];
#pragma unroll
                for (int j = 0; j < 4; j++) {
                    int mj = (j < 5 - D) ? 0 : (j - (4 - D));
                    s4[j] = (dd[di * 4 + mj] + td[di] + ud[mj] + c0) * scale;
                }
                float mx = fmaxf(fmaxf(s4[0], s4[1]), fmaxf(s4[2], s4[3]));
                float e0 = expf(s4[0] - mx), e1 = expf(s4[1] - mx);
                float e2 = expf(s4[2] - mx), e3 = expf(s4[3] - mx);
                float inv = 1.f / (e0 + e1 + e2 + e3);
                acc[di * 4 + 0] += logf(e0 * inv * rfac + 1e-4f);
                acc[di * 4 + 1] += logf(e1 * inv * rfac + 1e-4f);
                acc[di * 4 + 2] += logf(e2 * inv * rfac + 1e-4f);
                acc[di * 4 + 3] += logf(e3 * inv * rfac + 1e-4f);
            }
        }
    }
    __shared__ float sh[8][16];
    if (lane == 0)
#pragma unroll
        for (int m = 0; m < 16; m++) sh[wid][m] = acc[m];
    __syncthreads();
    int nw = blockDim.x >> 5;
    if (threadIdx.x < 16) {
        float s = 0.f;
        for (int w2 = 0; w2 < nw; w2++) s += sh[w2][threadIdx.x];
        atomicAdd(&Cm[threadIdx.x], s);
    }
}

template <int D>
__global__ void combine4(const float* __restrict__ a0, const float* __restrict__ a1,
                         const float* __restrict__ a2, const float* __restrict__ a3,
                         const float* __restrict__ CmAcc, float Ninv,
                         float* __restrict__ out, int n4) {
    int i = blockIdx.x * blockDim.x + threadIdx.x;
    if (i >= n4) return;
    float c[4];
    {
        float Mf[16];
#pragma unroll
        for (int r = 0; r < 4; r++) {
            int mr = (r < 5 - D) ? 0 : (r - (4 - D));
#pragma unroll
            for (int j = 0; j < 4; j++) Mf[r * 4 + j] = __ldg(&CmAcc[mr * 4 + j]) * Ninv;
        }
        float s = 0.f;
#pragma unroll
        for (int j = 0; j < 4; j++) { c[j] = 0.5f * (Mf[12 + j] + Mf[j * 4 + 3]); s += c[j]; }
        float invs = 1.f / s;
#pragma unroll
        for (int j = 0; j < 4; j++) c[j] *= invs;
    }
    float cd[4] = {0.f, 0.f, 0.f, 0.f};
#pragma unroll
    for (int o = 0; o < 4; o++) {
        int mo = (o < 5 - D) ? 0 : (o - (4 - D));
        cd[mo] += c[o];
    }
    const float* as[4] = {a0, a1, a2, a3};
    float4 o4 = make_float4(0.f, 0.f, 0.f, 0.f);
#pragma unroll
    for (int k = 0; k < D; k++) {
        float4 v = ((const float4*)as[k])[i];
        o4.x = fmaf(cd[k], v.x, o4.x);
        o4.y = fmaf(cd[k], v.y, o4.y);
        o4.z = fmaf(cd[k], v.z, o4.z);
        o4.w = fmaf(cd[k], v.w, o4.w);
    }
    ((float4*)out)[i] = o4;
}

// ---------------- persistent Chebyshev solve (bf16 Z, register X, 2-edge unroll) ----------------
__device__ __forceinline__ float4 bf16row_load(const __nv_bfloat16* p) {
    uint2 zz = *reinterpret_cast<const uint2*>(p);
    __nv_bfloat162 h0 = *reinterpret_cast<__nv_bfloat162*>(&zz.x);
    __nv_bfloat162 h1 = *reinterpret_cast<__nv_bfloat162*>(&zz.y);
    float2 f0 = __bfloat1622float2(h0), f1 = __bfloat1622float2(h1);
    return make_float4(f0.x, f0.y, f1.x, f1.y);
}
__device__ __forceinline__ void bf16row_store(__nv_bfloat16* p, float4 v) {
    __nv_bfloat162 h0 = __floats2bfloat162_rn(v.x, v.y);
    __nv_bfloat162 h1 = __floats2bfloat162_rn(v.z, v.w);
    uint2 zz;
    zz.x = *reinterpret_cast<uint32_t*>(&h0);
    zz.y = *reinterpret_cast<uint32_t*>(&h1);
    *reinterpret_cast<uint2*>(p) = zz;
}

__global__ __launch_bounds__(CGT, 1) void cheb_kernel(
    const float* __restrict__ T1, const float* __restrict__ A1,
    const float* __restrict__ A2, const float* __restrict__ AU,
    const float* __restrict__ bng, const float* __restrict__ bnb,
    const float* __restrict__ bnm, const float* __restrict__ bnv,
    const int* __restrict__ rowptr, const int* __restrict__ cols,
    const float* __restrict__ w, const float* __restrict__ Kap,
    float* __restrict__ X, __nv_bfloat16* __restrict__ ZA,
    __nv_bfloat16* __restrict__ ZB, int N) {
    const int tid = blockIdx.x * CGT + threadIdx.x;
    const int lane = threadIdx.x & 31;
    const int gw = tid >> 5;
    const int tw = (NBLK * CGT) >> 5;
    const int cl = lane * 4;

    float4 bg = *(const float4*)(bng + cl), bb = *(const float4*)(bnb + cl);
    float4 bm = *(const float4*)(bnm + cl), bv = *(const float4*)(bnv + cl);
    float4 kk = *(const float4*)(Kap + cl);
    float w1p[4], sg[4], ck[4];
    {
        float kd[4] = {kk.x, kk.y, kk.z, kk.w};
#pragma unroll
        for (int u = 0; u < 4; u++) {
            float k2 = fminf(fmaxf(kd[u], 0.f), 1.f);
            float hk = HCOEF * k2;
            float rt = sqrtf(1.f + 2.f * hk);
            float s = hk / (1.f + hk + rt);
            w1p[u] = 1.f + 1.f / rt;
            sg[u] = s;
            ck[u] = -2.f * s / rt;
        }
    }
    float bgs[4] = {bg.x * rsqrtf(bv.x + EPS_BN), bg.y * rsqrtf(bv.y + EPS_BN),
                    bg.z * rsqrtf(bv.z + EPS_BN), bg.w * rsqrtf(bv.w + EPS_BN)};

    float4 xl[MAXR];

    {
        int mi = 0;
        for (int r = gw; r < N; r += tw, mi++) {
            size_t off = (size_t)r * NH + cl;
            float4 t1 = *(const float4*)(T1 + off);
            float4 a1 = *(const float4*)(A1 + off);
            float4 a2 = *(const float4*)(A2 + off);
            float4 au = *(const float4*)(AU + off);
            float tt[4] = {t1.x, t1.y, t1.z, t1.w}, aa1[4] = {a1.x, a1.y, a1.z, a1.w};
            float aa2[4] = {a2.x, a2.y, a2.z, a2.w}, aau[4] = {au.x, au.y, au.z, au.w};
            float bbv[4] = {bb.x, bb.y, bb.z, bb.w}, bmv[4] = {bm.x, bm.y, bm.z, bm.w};
            float y[4], xv[4];
#pragma unroll
            for (int u = 0; u < 4; u++) {
                float d2 = fminf(fmaxf(aa2[u], -1.f), 1.f);
                float yy = tt[u] + HCOEF * (aa1[u] + aau[u] + tt[u] * d2);
                yy = (yy - bmv[u]) * bgs[u] + bbv[u];
                yy = (yy > 0.f) ? yy : expm1f(yy);
                y[u] = yy;
                xv[u] = w1p[u] * yy;
            }
            bf16row_store(ZA + off, make_float4(y[0], y[1], y[2], y[3]));
            xl[mi] = make_float4(xv[0], xv[1], xv[2], xv[3]);
        }
    }
    grid_barrier();

    float4 ckv = make_float4(ck[0], ck[1], ck[2], ck[3]);
    float4 sgv = make_float4(sg[0], sg[1], sg[2], sg[3]);

#pragma unroll
    for (int k = 1; k <= CHEB_M; k++) {
        const __nv_bfloat16* cur = (k & 1) ? ZA : ZB;
        __nv_bfloat16* oth = (k & 1) ? ZB : ZA;
        int mi = 0;
        for (int r = gw; r < N; r += tw, mi++) {
            int e0 = rowptr[r], e1 = rowptr[r + 1];
            float4 acc = make_float4(0.f, 0.f, 0.f, 0.f);
            int e = e0;
            // 2-edge unrolled gather: two independent load chains per iteration
            for (; e + 2 <= e1; e += 2) {
                int ca = __ldg(&cols[e]), cb = __ldg(&cols[e + 1]);
                float wa = __ldg(&w[e]), wb = __ldg(&w[e + 1]);
                float4 ya = bf16row_load(cur + (size_t)ca * NH + cl);
                float4 yb = bf16row_load(cur + (size_t)cb * NH + cl);
                acc.x = fmaf(wa, ya.x, acc.x); acc.y = fmaf(wa, ya.y, acc.y);
                acc.z = fmaf(wa, ya.z, acc.z); acc.w = fmaf(wa, ya.w, acc.w);
                acc.x = fmaf(wb, yb.x, acc.x); acc.y = fmaf(wb, yb.y, acc.y);
                acc.z = fmaf(wb, yb.z, acc.z); acc.w = fmaf(wb, yb.w, acc.w);
            }
            if (e < e1) {
                int c = __ldg(&cols[e]);
                float wt = __ldg(&w[e]);
                float4 y = bf16row_load(cur + (size_t)c * NH + cl);
                acc.x = fmaf(wt, y.x, acc.x); acc.y = fmaf(wt, y.y, acc.y);
                acc.z = fmaf(wt, y.z, acc.z); acc.w = fmaf(wt, y.w, acc.w);
            }
            size_t off = (size_t)r * NH + cl;
            float4 zn;
            if (k == 1) zn = acc;
            else {
                float4 zp = bf16row_load(oth + off);
                zn.x = 2.f * acc.x - zp.x; zn.y = 2.f * acc.y - zp.y;
                zn.z = 2.f * acc.z - zp.z; zn.w = 2.f * acc.w - zp.w;
            }
            float4 xv = xl[mi];
            xv.x = fmaf(ckv.x, zn.x, xv.x); xv.y = fmaf(ckv.y, zn.y, xv.y);
            xv.z = fmaf(ckv.z, zn.z, xv.z); xv.w = fmaf(ckv.w, zn.w, xv.w);
            xl[mi] = xv;
            if (k < CHEB_M) bf16row_store(oth + off, zn);
        }
        ckv.x *= -sgv.x; ckv.y *= -sgv.y; ckv.z *= -sgv.z; ckv.w *= -sgv.w;
        if (k < CHEB_M) grid_barrier();
    }

    {
        int mi = 0;
        for (int r = gw; r < N; r += tw, mi++)
            *(float4*)(X + (size_t)r * NH + cl) = xl[mi];
    }
}

// ---------------- host ----------------
extern "C" void kernel_launch(void* const* d_in, const int* in_sizes, int n_in,
                              void* d_out, int out_size) {
    const float* T      = (const float*)d_in[0];
    const int*   EI     = (const int*)d_in[1];
    const float* KopenW = (const float*)d_in[2];
    const float* Kopenb = (const float*)d_in[3];
    const float* bnOg   = (const float*)d_in[4];
    const float* bnOb   = (const float*)d_in[5];
    const float* bnOm   = (const float*)d_in[6];
    const float* bnOv   = (const float*)d_in[7];
    const float* convW  = (const float*)d_in[8];
    const float* convb  = (const float*)d_in[9];
    const float* bnAg   = (const float*)d_in[10];
    const float* bnAb   = (const float*)d_in[11];
    const float* bnAm   = (const float*)d_in[12];
    const float* bnAv   = (const float*)d_in[13];
    const float* Wq     = (const float*)d_in[14];
    const float* bq     = (const float*)d_in[15];
    const float* Wk     = (const float*)d_in[16];
    const float* bk     = (const float*)d_in[17];
    const float* mha    = (const float*)d_in[18];
    const float* KR1W   = (const float*)d_in[19];
    const float* KR1b   = (const float*)d_in[20];
    const float* KR2W   = (const float*)d_in[21];
    const float* KR2b   = (const float*)d_in[22];
    const float* KRU0W  = (const float*)d_in[23];
    const float* KRU0b  = (const float*)d_in[24];
    const float* bng    = (const float*)d_in[25];
    const float* bnbp   = (const float*)d_in[26];
    const float* bnm    = (const float*)d_in[27];
    const float* bnv    = (const float*)d_in[28];
    const float* Kappa  = (const float*)d_in[29];
    const float* KcloseW= (const float*)d_in[30];
    const float* Kcloseb= (const float*)d_in[31];

    const int N = in_sizes[0] / NH;
    const int E = in_sizes[1] / 2;
    const int n4 = N * (NH / 4);
    const size_t S = (size_t)MAXN * NH;

    float *Th, *z, *Xb, *vb, *T1, *A1, *A2, *AUb, *dinvp, *wp, *scal;
    float *Mg, *uvp, *tvp, *c0p, *zb;
    __nv_bfloat16 *WH, *WL, *ZA, *ZB;
    int *rowptr, *cnt, *bsum, *cols;
    cudaGetSymbolAddress((void**)&Th, d_Th);
    cudaGetSymbolAddress((void**)&z, d_z);
    cudaGetSymbolAddress((void**)&Xb, d_Xb);
    cudaGetSymbolAddress((void**)&vb, d_vb);
    cudaGetSymbolAddress((void**)&T1, d_T1);
    cudaGetSymbolAddress((void**)&A1, d_A1);
    cudaGetSymbolAddress((void**)&A2, d_A2);
    cudaGetSymbolAddress((void**)&AUb, d_AUb);
    cudaGetSymbolAddress((void**)&ZA, d_ZA);
    cudaGetSymbolAddress((void**)&ZB, d_ZB);
    cudaGetSymbolAddress((void**)&WH, d_WH);
    cudaGetSymbolAddress((void**)&WL, d_WL);
    cudaGetSymbolAddress((void**)&Mg, d_M);
    cudaGetSymbolAddress((void**)&uvp, d_uvec);
    cudaGetSymbolAddress((void**)&tvp, d_tvec);
    cudaGetSymbolAddress((void**)&c0p, d_c0s);
    cudaGetSymbolAddress((void**)&zb, d_zbias);
    cudaGetSymbolAddress((void**)&dinvp, d_dinv);
    cudaGetSymbolAddress((void**)&wp, d_w);
    cudaGetSymbolAddress((void**)&scal, d_scal);
    cudaGetSymbolAddress((void**)&rowptr, d_rowptr);
    cudaGetSymbolAddress((void**)&cnt, d_cnt);
    cudaGetSymbolAddress((void**)&bsum, d_bsum);
    cudaGetSymbolAddress((void**)&cols, d_cols);

    static bool attr_done = false;
    if (!attr_done) {
        cudaFuncSetAttribute(gemm_tc<0>, cudaFuncAttributeMaxDynamicSharedMemorySize, GSMEM);
        cudaFuncSetAttribute(gemm_tc<1>, cudaFuncAttributeMaxDynamicSharedMemorySize, GSMEM);
        cudaFuncSetAttribute(gemm_tc<2>, cudaFuncAttributeMaxDynamicSharedMemorySize, GSMEM);
        cudaFuncSetAttribute(gemm_tc_b4, cudaFuncAttributeMaxDynamicSharedMemorySize, GSMEM);
        attr_done = true;
    }

    const int GBX = (N + 63) / 64;
    dim3 gs1(GBX, 2), gs2(GBX, 4), gb4(GBX, 8), gcl(GBX, 1);
    const int VB = (n4 + 255) / 256;
    const float Ninv = 1.0f / (float)N;

    gram_kernel<<<66, 256>>>(Wq, Wk, bq, bk, Mg, uvp, tvp, c0p, scal, zb);

    WPtrs wpt;
    wpt.p[0] = KopenW; wpt.p[1] = convW; wpt.p[2] = Mg; wpt.p[3] = Mg;
    for (int j = 0; j < 4; j++) {
        wpt.p[4 + j] = KR1W + (size_t)j * WSLOT;
        wpt.p[8 + j] = KR2W + (size_t)j * WSLOT;
        wpt.p[12 + j] = KRU0W + (size_t)j * WSLOT;
    }
    wpt.p[16] = KcloseW;
    wconv_kernel<<<dim3(16, 17), 256>>>(wpt, WH, WL);

    csr_kernel<<<NBLK, CGT>>>(EI, E, N, cnt, dinvp, bsum, rowptr, cols, wp);

    gemm_tc<1><<<gs1, 256, GSMEM>>>(T, WH, WL, Kopenb, Th, WH, WL, Kopenb, Th, N, NH,
                                    bnOg, bnOb, bnOm, bnOv);
    gemm_tc<2><<<gs1, 256, GSMEM>>>(Th, WH + 1 * WSLOT, WL + 1 * WSLOT, convb, z,
                                    WH + 1 * WSLOT, WL + 1 * WSLOT, convb, z, N, NH,
                                    bnAg, bnAb, bnAm, bnAv);
    gemm_tc<0><<<gs1, 256, GSMEM>>>(z, WH + 2 * WSLOT, WL + 2 * WSLOT, zb, vb,
                                    WH + 2 * WSLOT, WL + 2 * WSLOT, zb, vb, N, NH, 0, 0, 0, 0);
    gemm_tc_b4<<<gb4, 256, GSMEM>>>(Th, WH + 12 * WSLOT, WL + 12 * WSLOT, KRU0b, AUb, S, N);

    for (int jj = 0; jj < 4; jj++) {
        const float* T1in;
        if (jj == 0) {
            T1in = z;  // all acts slots identical -> uniform softmax -> T1 == z exactly
        } else {
            gemm_tc<0><<<gs1, 256, GSMEM>>>(Xb + (jj - 1) * S,
                                            WH + 2 * WSLOT, WL + 2 * WSLOT, zb, vb + jj * S,
                                            WH + 2 * WSLOT, WL + 2 * WSLOT, zb, vb + jj * S,
                                            N, NH, 0, 0, 0, 0);
            const float *da[4] = {z, z, z, z};
            const float *dv[4] = {vb, vb, vb, vb};
            for (int m = 0; m < jj; m++) {
                da[m + 1] = Xb + m * S;
                dv[m + 1] = vb + (m + 1) * S;
            }
            float* sl = scal + jj * SSTR;
            if (jj == 1) {
                attn_kernel<2><<<400, 256>>>(da[0], da[1], da[2], da[3], dv[0], dv[1], dv[2], dv[3],
                                             uvp, tvp, c0p, mha, sl, N);
                combine4<2><<<VB, 256>>>(da[0], da[1], da[2], da[3], sl, Ninv, T1, n4);
            } else if (jj == 2) {
                attn_kernel<3><<<400, 256>>>(da[0], da[1], da[2], da[3], dv[0], dv[1], dv[2], dv[3],
                                             uvp, tvp, c0p, mha, sl, N);
                combine4<3><<<VB, 256>>>(da[0], da[1], da[2], da[3], sl, Ninv, T1, n4);
            } else {
                attn_kernel<4><<<400, 256>>>(da[0], da[1], da[2], da[3], dv[0], dv[1], dv[2], dv[3],
                                             uvp, tvp, c0p, mha, sl, N);
                combine4<4><<<VB, 256>>>(da[0], da[1], da[2], da[3], sl, Ninv, T1, n4);
            }
            T1in = T1;
        }

        gemm_tc<0><<<gs2, 256, GSMEM>>>(T1in,
                                        WH + (4 + jj) * WSLOT, WL + (4 + jj) * WSLOT,
                                        KR1b + jj * NH, A1,
                                        WH + (8 + jj) * WSLOT, WL + (8 + jj) * WSLOT,
                                        KR2b + jj * NH, A2, N, NH, 0, 0, 0, 0);

        cheb_kernel<<<NBLK, CGT>>>(T1in, A1, A2, AUb + jj * S, bng + jj * NH, bnbp + jj * NH,
                                   bnm + jj * NH, bnv + jj * NH, rowptr, cols, wp,
                                   Kappa + jj * NH, Xb + jj * S, ZA, ZB, N);
    }
    gemm_tc<0><<<gcl, 256, GSMEM>>>(Xb + 3 * S, WH + 16 * WSLOT, WL + 16 * WSLOT, Kcloseb,
                                    (float*)d_out, WH + 16 * WSLOT, WL + 16 * WSLOT, Kcloseb,
                                    (float*)d_out, N, 40, 0, 0, 0, 0);
}

// round 17
// speedup vs baseline: 1.0721x; 1.0073x over previous
#include <cuda_runtime.h>
#include <cuda_bf16.h>
#include <math.h>
#include <stdint.h>

#define NH 128
#define MAXN 50000
#define MAXE 800000
#define HCOEF 0.1f
#define EPS_BN 1e-5f
#define SSTR 48
#define NBLK 148
#define CGT 1024
#define WSLOT (NH * NH)

// ---------------- device scratch ----------------
__device__ float d_Th[MAXN * NH];
__device__ float d_z[MAXN * NH];
__device__ float d_Xb[4][MAXN * NH];
__device__ float d_vb[4][MAXN * NH];
__device__ float d_T1[MAXN * NH];
__device__ float d_Trf[MAXN * NH];
__device__ float d_A1[MAXN * NH];
__device__ float d_A2[MAXN * NH];
__device__ float d_AUb[4][MAXN * NH];
__device__ __nv_bfloat16 d_ZA[MAXN * NH];
__device__ __nv_bfloat16 d_ZB[MAXN * NH];
__device__ __nv_bfloat16 d_WH[17 * WSLOT];
__device__ __nv_bfloat16 d_WL[17 * WSLOT];
__device__ float d_M[WSLOT];
__device__ float d_uvec[NH];
__device__ float d_tvec[NH];
__device__ float d_c0s[1];
__device__ float d_zbias[NH];
__device__ int   d_rowptr[MAXN + 1];
__device__ int   d_cnt[MAXN];
__device__ int   d_bsum[64];
__device__ int   d_cols[MAXE];
__device__ float d_w[MAXE];
__device__ float d_dinv[MAXN];
__device__ float d_scal[4 * SSTR];
__device__ volatile unsigned d_barcnt = 0;
__device__ volatile unsigned d_bargen = 0;

__device__ __forceinline__ void grid_barrier() {
    __syncthreads();
    if (threadIdx.x == 0) {
        unsigned g = d_bargen;
        __threadfence();
        unsigned a = atomicInc((unsigned*)&d_barcnt, NBLK - 1);
        if (a == NBLK - 1) {
            __threadfence();
            d_bargen = g + 1;
        } else {
            while (d_bargen == g) __nanosleep(128);
        }
        __threadfence();
    }
    __syncthreads();
}

// ---------------- persistent CSR build ----------------
__global__ __launch_bounds__(CGT, 1) void csr_kernel(
    const int* __restrict__ EI, int E, int N,
    int* __restrict__ cnt, float* __restrict__ dinv, int* __restrict__ bsum,
    int* __restrict__ rowptr, int* __restrict__ cols, float* __restrict__ w) {
    const int tid = blockIdx.x * CGT + threadIdx.x;
    const int nth = NBLK * CGT;
    __shared__ int sh[1024];
    const int nb = (N + 1023) / 1024;

    for (int i = tid; i < N; i += nth) cnt[i] = 0;
    grid_barrier();
    for (int e = tid; e < E; e += nth) {
        int r = EI[e], c = EI[E + e];
        if (r != c) atomicAdd(&cnt[r], 1);
    }
    grid_barrier();
    if (blockIdx.x < nb) {
        int i = blockIdx.x * 1024 + threadIdx.x;
        int x = (i < N) ? cnt[i] : 0;
        if (i < N) dinv[i] = (x > 0) ? rsqrtf((float)x) : 0.f;
        sh[threadIdx.x] = x;
        __syncthreads();
        for (int o = 512; o; o >>= 1) {
            if (threadIdx.x < o) sh[threadIdx.x] += sh[threadIdx.x + o];
            __syncthreads();
        }
        if (threadIdx.x == 0) bsum[blockIdx.x] = sh[0];
    }
    grid_barrier();
    if (blockIdx.x == 0 && threadIdx.x == 0) {
        int run = 0;
        for (int i = 0; i < nb; i++) { int t = bsum[i]; bsum[i] = run; run += t; }
        rowptr[N] = run;
    }
    grid_barrier();
    if (blockIdx.x < nb) {
        int i = blockIdx.x * 1024 + threadIdx.x;
        int x = (i < N) ? cnt[i] : 0;
        sh[threadIdx.x] = x;
        __syncthreads();
        for (int off = 1; off < 1024; off <<= 1) {
            int t = (threadIdx.x >= off) ? sh[threadIdx.x - off] : 0;
            __syncthreads();
            sh[threadIdx.x] += t;
            __syncthreads();
        }
        if (i < N) {
            int excl = sh[threadIdx.x] - x + bsum[blockIdx.x];
            rowptr[i] = excl;
            cnt[i] = excl;
        }
    }
    grid_barrier();
    for (int e = tid; e < E; e += nth) {
        int r = EI[e], c = EI[E + e];
        if (r != c) {
            int pos = atomicAdd(&cnt[r], 1);
            cols[pos] = c;
            w[pos] = -dinv[r] * dinv[c];
        }
    }
}

// ---------------- Gram precompute (+ zero scal/zb) ----------------
__global__ void gram_kernel(const float* __restrict__ Wq, const float* __restrict__ Wk,
                            const float* __restrict__ bq, const float* __restrict__ bk,
                            float* __restrict__ M, float* __restrict__ uv,
                            float* __restrict__ tv, float* __restrict__ c0,
                            float* __restrict__ scal, float* __restrict__ zb) {
    if (blockIdx.x < 64) {
        int idx = blockIdx.x * 256 + threadIdx.x;
        int e = idx >> 7, f = idx & 127;
        float s = 0.f;
        for (int d = 0; d < 128; d++)
            s = fmaf(__ldg(&Wq[d * 128 + e]), __ldg(&Wk[d * 128 + f]), s);
        M[e * 128 + f] = s;
    } else if (blockIdx.x == 64) {
        if (threadIdx.x < 128) {
            int f = threadIdx.x;
            float su = 0.f, st = 0.f;
            for (int d = 0; d < 128; d++) {
                su = fmaf(__ldg(&bq[d]), __ldg(&Wk[d * 128 + f]), su);
                st = fmaf(__ldg(&bk[d]), __ldg(&Wq[d * 128 + f]), st);
            }
            uv[f] = su;
            tv[f] = st;
            if (f == 0) {
                float s = 0.f;
                for (int d = 0; d < 128; d++) s = fmaf(bq[d], bk[d], s);
                *c0 = s;
            }
        }
    } else {
        if (threadIdx.x < 4 * SSTR) scal[threadIdx.x] = 0.f;
        int zi = threadIdx.x - 4 * SSTR;
        if (zi >= 0 && zi < NH) zb[zi] = 0.f;
    }
}

// ---------------- weight pre-conversion ----------------
struct WPtrs { const float* p[17]; };

__global__ void wconv_kernel(WPtrs wp, __nv_bfloat16* WH, __nv_bfloat16* WL) {
    int slot = blockIdx.y;
    int rows = (slot == 16) ? 40 : 128;
    int i = (blockIdx.x * 256 + threadIdx.x) * 4;
    int row = i >> 7;
    __nv_bfloat16* wh = WH + (size_t)slot * WSLOT + i;
    __nv_bfloat16* wl = WL + (size_t)slot * WSLOT + i;
    if (row < rows) {
        float4 v = *(const float4*)(wp.p[slot] + i);
        float a[4] = {v.x, v.y, v.z, v.w};
#pragma unroll
        for (int u = 0; u < 4; u++) {
            __nv_bfloat16 h = __float2bfloat16(a[u]);
            wh[u] = h;
            wl[u] = __float2bfloat16(a[u] - __bfloat162float(h));
        }
    } else {
#pragma unroll
        for (int u = 0; u < 4; u++) { wh[u] = __float2bfloat16(0.f); wl[u] = __float2bfloat16(0.f); }
    }
}

// ---------------- tensor-core GEMM: 64x64 tiles, fused 3-term split, 3 CTA/SM ----------------
__device__ __forceinline__ void mma16816(float* c, const uint32_t* a, const uint32_t* b) {
    asm volatile(
        "mma.sync.aligned.m16n8k16.row.col.f32.bf16.bf16.f32 "
        "{%0,%1,%2,%3}, {%4,%5,%6,%7}, {%8,%9}, {%0,%1,%2,%3};\n"
        : "+f"(c[0]), "+f"(c[1]), "+f"(c[2]), "+f"(c[3])
        : "r"(a[0]), "r"(a[1]), "r"(a[2]), "r"(a[3]), "r"(b[0]), "r"(b[1]));
}
__device__ __forceinline__ void ldsm4(uint32_t* d, uint32_t addr) {
    asm volatile("ldmatrix.sync.aligned.m8n8.x4.shared.b16 {%0,%1,%2,%3}, [%4];"
                 : "=r"(d[0]), "=r"(d[1]), "=r"(d[2]), "=r"(d[3]) : "r"(addr));
}
__device__ __forceinline__ void ldsm2(uint32_t* d, uint32_t addr) {
    asm volatile("ldmatrix.sync.aligned.m8n8.x2.shared.b16 {%0,%1}, [%2];"
                 : "=r"(d[0]), "=r"(d[1]) : "r"(addr));
}
__device__ __forceinline__ void cp_async16(uint32_t dst, const void* src) {
    asm volatile("cp.async.cg.shared.global [%0], [%1], 16;" :: "r"(dst), "l"(src));
}

#define LDW 136
#define GSMEM (4 * 64 * LDW * 2)

template <int EPI>
__device__ __forceinline__ void gemm_body(
    const float* __restrict__ A,
    const __nv_bfloat16* __restrict__ WHp, const __nv_bfloat16* __restrict__ WLp,
    const float* __restrict__ bsel, float* __restrict__ Csel, int N, int Oc, int colbase,
    const float* __restrict__ bng, const float* __restrict__ bnb,
    const float* __restrict__ bnm, const float* __restrict__ bnv) {
    extern __shared__ __align__(16) char smem_raw[];
    __nv_bfloat16* Ah = (__nv_bfloat16*)smem_raw;
    __nv_bfloat16* Al = Ah + 64 * LDW;
    __nv_bfloat16* Wh = Al + 64 * LDW;
    __nv_bfloat16* Wl = Wh + 64 * LDW;

    const int tid = threadIdx.x;
    const int brow = blockIdx.x * 64;

    uint32_t sAh = (uint32_t)__cvta_generic_to_shared(Ah);
    uint32_t sAl = (uint32_t)__cvta_generic_to_shared(Al);
    uint32_t sWh = (uint32_t)__cvta_generic_to_shared(Wh);
    uint32_t sWl = (uint32_t)__cvta_generic_to_shared(Wl);

#pragma unroll
    for (int i = 0; i < 4; i++) {
        int ch = i * 256 + tid;
        int row = ch >> 4, cc = ch & 15;
        cp_async16(sWh + (uint32_t)(row * (LDW * 2) + cc * 16),
                   (const char*)WHp + (size_t)(colbase + row) * 256 + cc * 16);
    }
#pragma unroll
    for (int i = 0; i < 4; i++) {
        int ch = i * 256 + tid;
        int row = ch >> 4, cc = ch & 15;
        cp_async16(sWl + (uint32_t)(row * (LDW * 2) + cc * 16),
                   (const char*)WLp + (size_t)(colbase + row) * 256 + cc * 16);
    }
    asm volatile("cp.async.commit_group;");

#pragma unroll
    for (int i = 0; i < 8; i++) {
        int fl = i * 256 + tid;
        int row = fl >> 5;
        int c4 = (fl & 31) << 2;
        float4 av = make_float4(0.f, 0.f, 0.f, 0.f);
        int gr = brow + row;
        if (gr < N) av = *(const float4*)(A + (size_t)gr * 128 + c4);
        float a[4] = {av.x, av.y, av.z, av.w};
        uint32_t hp[2], lp[2];
#pragma unroll
        for (int h2 = 0; h2 < 2; h2++) {
            __nv_bfloat16 h0 = __float2bfloat16(a[h2 * 2]);
            __nv_bfloat16 h1 = __float2bfloat16(a[h2 * 2 + 1]);
            __nv_bfloat16 l0 = __float2bfloat16(a[h2 * 2] - __bfloat162float(h0));
            __nv_bfloat16 l1 = __float2bfloat16(a[h2 * 2 + 1] - __bfloat162float(h1));
            hp[h2] = ((uint32_t)__bfloat16_as_ushort(h1) << 16) | __bfloat16_as_ushort(h0);
            lp[h2] = ((uint32_t)__bfloat16_as_ushort(l1) << 16) | __bfloat16_as_ushort(l0);
        }
        int base = row * LDW + c4;
        *(uint2*)&Ah[base] = make_uint2(hp[0], hp[1]);
        *(uint2*)&Al[base] = make_uint2(lp[0], lp[1]);
    }
    asm volatile("cp.async.wait_group 0;");
    __syncthreads();

    const int w = tid >> 5, lane = tid & 31;
    const int wm = w >> 2, wn = w & 3;

    float acc[2][2][4];
#pragma unroll
    for (int mt = 0; mt < 2; mt++)
#pragma unroll
        for (int nt = 0; nt < 2; nt++)
#pragma unroll
            for (int u = 0; u < 4; u++) acc[mt][nt][u] = 0.f;

#pragma unroll
    for (int kk = 0; kk < 8; kk++) {
        uint32_t bh[2][2], bl[2][2];
        {
            int r = lane & 7, sel = (lane >> 3) & 1;
            int kcol = kk * 16 + sel * 8;
#pragma unroll
            for (int nt = 0; nt < 2; nt++) {
                int row = wn * 16 + nt * 8 + r;
                uint32_t off = (uint32_t)(row * LDW + kcol) * 2;
                ldsm2(bh[nt], sWh + off);
                ldsm2(bl[nt], sWl + off);
            }
        }
        uint32_t ah[2][4], al[2][4];
        {
            int q = lane >> 3, r = lane & 7;
            int kcol = kk * 16 + (q >> 1) * 8;
#pragma unroll
            for (int mt = 0; mt < 2; mt++) {
                int row = wm * 32 + mt * 16 + (q & 1) * 8 + r;
                uint32_t off = (uint32_t)(row * LDW + kcol) * 2;
                ldsm4(ah[mt], sAh + off);
                ldsm4(al[mt], sAl + off);
            }
        }
#pragma unroll
        for (int mt = 0; mt < 2; mt++)
#pragma unroll
            for (int nt = 0; nt < 2; nt++) {
                mma16816(acc[mt][nt], ah[mt], bh[nt]);
                mma16816(acc[mt][nt], al[mt], bh[nt]);
                mma16816(acc[mt][nt], ah[mt], bl[nt]);
            }
    }

    const int g = lane >> 2, t2 = (lane & 3) * 2;
#pragma unroll
    for (int mt = 0; mt < 2; mt++) {
#pragma unroll
        for (int nt = 0; nt < 2; nt++) {
            int col0 = colbase + wn * 16 + nt * 8 + t2;
#pragma unroll
            for (int half = 0; half < 2; half++) {
                int row = brow + wm * 32 + mt * 16 + g + half * 8;
                if (row >= N) continue;
#pragma unroll
                for (int u = 0; u < 2; u++) {
                    int col = col0 + u;
                    if (col >= Oc) continue;
                    float x = acc[mt][nt][half * 2 + u] + bsel[col];
                    if (EPI) {
                        float s = bng[col] * rsqrtf(bnv[col] + EPS_BN);
                        x = (x - bnm[col]) * s + bnb[col];
                        if (EPI == 1) x = (x > 0.f) ? x : expm1f(x);
                        else x = fmaxf(x, 0.f);
                    }
                    Csel[(size_t)row * Oc + col] = x;
                }
            }
        }
    }
}

template <int EPI>
__global__ __launch_bounds__(256, 3) void gemm_tc(
    const float* __restrict__ A,
    const __nv_bfloat16* WH1, const __nv_bfloat16* WL1, const float* b1, float* C1,
    const __nv_bfloat16* WH2, const __nv_bfloat16* WL2, const float* b2, float* C2,
    int N, int Oc,
    const float* __restrict__ bng, const float* __restrict__ bnb,
    const float* __restrict__ bnm, const float* __restrict__ bnv) {
    int sel = blockIdx.y >> 1, ch = blockIdx.y & 1;
    gemm_body<EPI>(A, sel ? WH2 : WH1, sel ? WL2 : WL1, sel ? b2 : b1,
                   sel ? C2 : C1, N, Oc, ch * 64, bng, bnb, bnm, bnv);
}

__global__ __launch_bounds__(256, 3) void gemm_tc_b4(
    const float* __restrict__ A, const __nv_bfloat16* WHb, const __nv_bfloat16* WLb,
    const float* __restrict__ bb, float* __restrict__ Cb, size_t Cstride, int N) {
    int slot = blockIdx.y >> 1, ch = blockIdx.y & 1;
    gemm_body<0>(A, WHb + (size_t)slot * WSLOT, WLb + (size_t)slot * WSLOT,
                 bb + (size_t)slot * NH, Cb + (size_t)slot * Cstride,
                 N, NH, ch * 64, 0, 0, 0, 0);
}

// ---------------- attention stats, templated on D distinct slots ----------------
template <int D>
__global__ void attn_kernel(const float* __restrict__ a0, const float* __restrict__ a1,
                            const float* __restrict__ a2, const float* __restrict__ a3,
                            const float* __restrict__ v0, const float* __restrict__ v1,
                            const float* __restrict__ v2, const float* __restrict__ v3,
                            const float* __restrict__ uvp, const float* __restrict__ tvp,
                            const float* __restrict__ c0p,
                            const float* __restrict__ mha, float* __restrict__ Cm, int N) {
    const float scale = 0.08838834764831845f;
    float rfac = fmaxf(mha[0], 0.f);
    float c0 = *c0p;
    int lane = threadIdx.x & 31, wid = threadIdx.x >> 5;
    int gw = blockIdx.x * (blockDim.x >> 5) + wid;
    int tw = gridDim.x * (blockDim.x >> 5);
    const float* as[4] = {a0, a1, a2, a3};
    const float* vs[4] = {v0, v1, v2, v3};
    float4 u4 = *(const float4*)(uvp + lane * 4);
    float4 t4 = *(const float4*)(tvp + lane * 4);
    float acc[16];
#pragma unroll
    for (int m = 0; m < 16; m++) acc[m] = 0.f;
    for (int n = gw; n < N; n += tw) {
        float4 av[D], vv[D];
#pragma unroll
        for (int s = 0; s < D; s++) {
            av[s] = *(const float4*)(as[s] + (size_t)n * NH + lane * 4);
            vv[s] = *(const float4*)(vs[s] + (size_t)n * NH + lane * 4);
        }
        float dd[16], td[4], ud[4];
#pragma unroll
        for (int k = 0; k < D; k++)
#pragma unroll
            for (int l = 0; l < D; l++) {
                float4 a = av[k], b = vv[l];
                float v = a.x * b.x + a.y * b.y + a.z * b.z + a.w * b.w;
#pragma unroll
                for (int o = 16; o; o >>= 1) v += __shfl_xor_sync(0xffffffffu, v, o);
                dd[k * 4 + l] = v;
            }
#pragma unroll
        for (int k = 0; k < D; k++) {
            float4 a = av[k];
            float vt = t4.x * a.x + t4.y * a.y + t4.z * a.z + t4.w * a.w;
            float vu = u4.x * a.x + u4.y * a.y + u4.z * a.z + u4.w * a.w;
#pragma unroll
            for (int o = 16; o; o >>= 1) {
                vt += __shfl_xor_sync(0xffffffffu, vt, o);
                vu += __shfl_xor_sync(0xffffffffu, vu, o);
            }
            td[k] = vt;
            ud[k] = vu;
        }
        if (lane == 0) {
#pragma unroll
            for (int di = 0; di < D; di++) {
                float s4[4];
#pragma unroll
                for (int j = 0; j < 4; j++) {
                    int mj = (j < 5 - D) ? 0 : (j - (4 - D));
                    s4[j] = (dd[di * 4 + mj] + td[di] + ud[mj] + c0) * scale;
                }
                float mx = fmaxf(fmaxf(s4[0], s4[1]), fmaxf(s4[2], s4[3]));
                float e0 = expf(s4[0] - mx), e1 = expf(s4[1] - mx);
                float e2 = expf(s4[2] - mx), e3 = expf(s4[3] - mx);
                float inv = 1.f / (e0 + e1 + e2 + e3);
                acc[di * 4 + 0] += logf(e0 * inv * rfac + 1e-4f);
                acc[di * 4 + 1] += logf(e1 * inv * rfac + 1e-4f);
                acc[di * 4 + 2] += logf(e2 * inv * rfac + 1e-4f);
                acc[di * 4 + 3] += logf(e3 * inv * rfac + 1e-4f);
            }
        }
    }
    __shared__ float sh[8][16];
    if (lane == 0)
#pragma unroll
        for (int m = 0; m < 16; m++) sh[wid][m] = acc[m];
    __syncthreads();
    int nw = blockDim.x >> 5;
    if (threadIdx.x < 16) {
        float s = 0.f;
        for (int w2 = 0; w2 < nw; w2++) s += sh[w2][threadIdx.x];
        atomicAdd(&Cm[threadIdx.x], s);
    }
}

template <int D>
__global__ void combine4(const float* __restrict__ a0, const float* __restrict__ a1,
                         const float* __restrict__ a2, const float* __restrict__ a3,
                         const float* __restrict__ CmAcc, float Ninv,
                         float* __restrict__ out, int n4) {
    int i = blockIdx.x * blockDim.x + threadIdx.x;
    if (i >= n4) return;
    float c[4];
    {
        float Mf[16];
#pragma unroll
        for (int r = 0; r < 4; r++) {
            int mr = (r < 5 - D) ? 0 : (r - (4 - D));
#pragma unroll
            for (int j = 0; j < 4; j++) Mf[r * 4 + j] = __ldg(&CmAcc[mr * 4 + j]) * Ninv;
        }
        float s = 0.f;
#pragma unroll
        for (int j = 0; j < 4; j++) { c[j] = 0.5f * (Mf[12 + j] + Mf[j * 4 + 3]); s += c[j]; }
        float invs = 1.f / s;
#pragma unroll
        for (int j = 0; j < 4; j++) c[j] *= invs;
    }
    float cd[4] = {0.f, 0.f, 0.f, 0.f};
#pragma unroll
    for (int o = 0; o < 4; o++) {
        int mo = (o < 5 - D) ? 0 : (o - (4 - D));
        cd[mo] += c[o];
    }
    const float* as[4] = {a0, a1, a2, a3};
    float4 o4 = make_float4(0.f, 0.f, 0.f, 0.f);
#pragma unroll
    for (int k = 0; k < D; k++) {
        float4 v = ((const float4*)as[k])[i];
        o4.x = fmaf(cd[k], v.x, o4.x);
        o4.y = fmaf(cd[k], v.y, o4.y);
        o4.z = fmaf(cd[k], v.z, o4.z);
        o4.w = fmaf(cd[k], v.w, o4.w);
    }
    ((float4*)out)[i] = o4;
}

// ---------------- persistent Chebyshev m=2, closed-form, no row-register array ----------------
__device__ __forceinline__ float4 bf16row_load(const __nv_bfloat16* p) {
    uint2 zz = *reinterpret_cast<const uint2*>(p);
    __nv_bfloat162 h0 = *reinterpret_cast<__nv_bfloat162*>(&zz.x);
    __nv_bfloat162 h1 = *reinterpret_cast<__nv_bfloat162*>(&zz.y);
    float2 f0 = __bfloat1622float2(h0), f1 = __bfloat1622float2(h1);
    return make_float4(f0.x, f0.y, f1.x, f1.y);
}
__device__ __forceinline__ void bf16row_store(__nv_bfloat16* p, float4 v) {
    __nv_bfloat162 h0 = __floats2bfloat162_rn(v.x, v.y);
    __nv_bfloat162 h1 = __floats2bfloat162_rn(v.z, v.w);
    uint2 zz;
    zz.x = *reinterpret_cast<uint32_t*>(&h0);
    zz.y = *reinterpret_cast<uint32_t*>(&h1);
    *reinterpret_cast<uint2*>(p) = zz;
}

// X = (1+w)*Trf + c1*Z1 + c2*(2*S*Z1 - Trf);  Z1 = S*Tr
__global__ __launch_bounds__(CGT, 1) void cheb_kernel(
    const float* __restrict__ T1, const float* __restrict__ A1,
    const float* __restrict__ A2, const float* __restrict__ AU,
    const float* __restrict__ bng, const float* __restrict__ bnb,
    const float* __restrict__ bnm, const float* __restrict__ bnv,
    const int* __restrict__ rowptr, const int* __restrict__ cols,
    const float* __restrict__ w, const float* __restrict__ Kap,
    float* __restrict__ X, float* __restrict__ Trf,
    __nv_bfloat16* __restrict__ ZA, __nv_bfloat16* __restrict__ ZB, int N) {
    const int tid = blockIdx.x * CGT + threadIdx.x;
    const int lane = threadIdx.x & 31;
    const int gw = tid >> 5;
    const int tw = (NBLK * CGT) >> 5;
    const int cl = lane * 4;

    float4 bg = *(const float4*)(bng + cl), bb = *(const float4*)(bnb + cl);
    float4 bm = *(const float4*)(bnm + cl), bv = *(const float4*)(bnv + cl);
    float4 kk = *(const float4*)(Kap + cl);
    float w1p[4], c1[4], c2[4];
    {
        float kd[4] = {kk.x, kk.y, kk.z, kk.w};
#pragma unroll
        for (int u = 0; u < 4; u++) {
            float k2 = fminf(fmaxf(kd[u], 0.f), 1.f);
            float hk = HCOEF * k2;
            float rt = sqrtf(1.f + 2.f * hk);
            float s = hk / (1.f + hk + rt);
            w1p[u] = 1.f + 1.f / rt;
            c1[u] = -2.f * s / rt;
            c2[u] = -c1[u] * s;
        }
    }
    float bgs[4] = {bg.x * rsqrtf(bv.x + EPS_BN), bg.y * rsqrtf(bv.y + EPS_BN),
                    bg.z * rsqrtf(bv.z + EPS_BN), bg.w * rsqrtf(bv.w + EPS_BN)};

    // ---- prologue: Tr; store Trf fp32 + ZA bf16 ----
    for (int r = gw; r < N; r += tw) {
        size_t off = (size_t)r * NH + cl;
        float4 t1 = *(const float4*)(T1 + off);
        float4 a1 = *(const float4*)(A1 + off);
        float4 a2 = *(const float4*)(A2 + off);
        float4 au = *(const float4*)(AU + off);
        float tt[4] = {t1.x, t1.y, t1.z, t1.w}, aa1[4] = {a1.x, a1.y, a1.z, a1.w};
        float aa2[4] = {a2.x, a2.y, a2.z, a2.w}, aau[4] = {au.x, au.y, au.z, au.w};
        float bbv[4] = {bb.x, bb.y, bb.z, bb.w}, bmv[4] = {bm.x, bm.y, bm.z, bm.w};
        float y[4];
#pragma unroll
        for (int u = 0; u < 4; u++) {
            float d2 = fminf(fmaxf(aa2[u], -1.f), 1.f);
            float yy = tt[u] + HCOEF * (aa1[u] + aau[u] + tt[u] * d2);
            yy = (yy - bmv[u]) * bgs[u] + bbv[u];
            yy = (yy > 0.f) ? yy : expm1f(yy);
            y[u] = yy;
        }
        float4 yv = make_float4(y[0], y[1], y[2], y[3]);
        *(float4*)(Trf + off) = yv;
        bf16row_store(ZA + off, yv);
    }
    grid_barrier();

    // ---- sweep1: Z1 = S*Tr -> ZB (2-edge unrolled) ----
    for (int r = gw; r < N; r += tw) {
        int e0 = rowptr[r], e1 = rowptr[r + 1];
        float4 acc = make_float4(0.f, 0.f, 0.f, 0.f);
        int e = e0;
        for (; e + 2 <= e1; e += 2) {
            int ca = __ldg(&cols[e]), cb = __ldg(&cols[e + 1]);
            float wa = __ldg(&w[e]), wb = __ldg(&w[e + 1]);
            float4 ya = bf16row_load(ZA + (size_t)ca * NH + cl);
            float4 yb = bf16row_load(ZA + (size_t)cb * NH + cl);
            acc.x = fmaf(wa, ya.x, acc.x); acc.y = fmaf(wa, ya.y, acc.y);
            acc.z = fmaf(wa, ya.z, acc.z); acc.w = fmaf(wa, ya.w, acc.w);
            acc.x = fmaf(wb, yb.x, acc.x); acc.y = fmaf(wb, yb.y, acc.y);
            acc.z = fmaf(wb, yb.z, acc.z); acc.w = fmaf(wb, yb.w, acc.w);
        }
        if (e < e1) {
            int c = __ldg(&cols[e]);
            float wt = __ldg(&w[e]);
            float4 y = bf16row_load(ZA + (size_t)c * NH + cl);
            acc.x = fmaf(wt, y.x, acc.x); acc.y = fmaf(wt, y.y, acc.y);
            acc.z = fmaf(wt, y.z, acc.z); acc.w = fmaf(wt, y.w, acc.w);
        }
        bf16row_store(ZB + (size_t)r * NH + cl, acc);
    }
    grid_barrier();

    // ---- sweep2: acc = S*Z1; X = w1p*Trf + c1*Z1 + c2*(2*acc - Trf) ----
    for (int r = gw; r < N; r += tw) {
        int e0 = rowptr[r], e1 = rowptr[r + 1];
        float4 acc = make_float4(0.f, 0.f, 0.f, 0.f);
        int e = e0;
        for (; e + 2 <= e1; e += 2) {
            int ca = __ldg(&cols[e]), cb = __ldg(&cols[e + 1]);
            float wa = __ldg(&w[e]), wb = __ldg(&w[e + 1]);
            float4 ya = bf16row_load(ZB + (size_t)ca * NH + cl);
            float4 yb = bf16row_load(ZB + (size_t)cb * NH + cl);
            acc.x = fmaf(wa, ya.x, acc.x); acc.y = fmaf(wa, ya.y, acc.y);
            acc.z = fmaf(wa, ya.z, acc.z); acc.w = fmaf(wa, ya.w, acc.w);
            acc.x = fmaf(wb, yb.x, acc.x); acc.y = fmaf(wb, yb.y, acc.y);
            acc.z = fmaf(wb, yb.z, acc.z); acc.w = fmaf(wb, yb.w, acc.w);
        }
        if (e < e1) {
            int c = __ldg(&cols[e]);
            float wt = __ldg(&w[e]);
            float4 y = bf16row_load(ZB + (size_t)c * NH + cl);
            acc.x = fmaf(wt, y.x, acc.x); acc.y = fmaf(wt, y.y, acc.y);
            acc.z = fmaf(wt, y.z, acc.z); acc.w = fmaf(wt, y.w, acc.w);
        }
        size_t off = (size_t)r * NH + cl;
        float4 z1 = bf16row_load(ZB + off);
        float4 trf = *(const float4*)(Trf + off);
        float4 xv;
        xv.x = w1p[0] * trf.x + c1[0] * z1.x + c2[0] * (2.f * acc.x - trf.x);
        xv.y = w1p[1] * trf.y + c1[1] * z1.y + c2[1] * (2.f * acc.y - trf.y);
        xv.z = w1p[2] * trf.z + c1[2] * z1.z + c2[2] * (2.f * acc.z - trf.z);
        xv.w = w1p[3] * trf.w + c1[3] * z1.w + c2[3] * (2.f * acc.w - trf.w);
        *(float4*)(X + off) = xv;
    }
}

// ---------------- host ----------------
extern "C" void kernel_launch(void* const* d_in, const int* in_sizes, int n_in,
                              void* d_out, int out_size) {
    const float* T      = (const float*)d_in[0];
    const int*   EI     = (const int*)d_in[1];
    const float* KopenW = (const float*)d_in[2];
    const float* Kopenb = (const float*)d_in[3];
    const float* bnOg   = (const float*)d_in[4];
    const float* bnOb   = (const float*)d_in[5];
    const float* bnOm   = (const float*)d_in[6];
    const float* bnOv   = (const float*)d_in[7];
    const float* convW  = (const float*)d_in[8];
    const float* convb  = (const float*)d_in[9];
    const float* bnAg   = (const float*)d_in[10];
    const float* bnAb   = (const float*)d_in[11];
    const float* bnAm   = (const float*)d_in[12];
    const float* bnAv   = (const float*)d_in[13];
    const float* Wq     = (const float*)d_in[14];
    const float* bq     = (const float*)d_in[15];
    const float* Wk     = (const float*)d_in[16];
    const float* bk     = (const float*)d_in[17];
    const float* mha    = (const float*)d_in[18];
    const float* KR1W   = (const float*)d_in[19];
    const float* KR1b   = (const float*)d_in[20];
    const float* KR2W   = (const float*)d_in[21];
    const float* KR2b   = (const float*)d_in[22];
    const float* KRU0W  = (const float*)d_in[23];
    const float* KRU0b  = (const float*)d_in[24];
    const float* bng    = (const float*)d_in[25];
    const float* bnbp   = (const float*)d_in[26];
    const float* bnm    = (const float*)d_in[27];
    const float* bnv    = (const float*)d_in[28];
    const float* Kappa  = (const float*)d_in[29];
    const float* KcloseW= (const float*)d_in[30];
    const float* Kcloseb= (const float*)d_in[31];

    const int N = in_sizes[0] / NH;
    const int E = in_sizes[1] / 2;
    const int n4 = N * (NH / 4);
    const size_t S = (size_t)MAXN * NH;

    float *Th, *z, *Xb, *vb, *T1, *Trf, *A1, *A2, *AUb, *dinvp, *wp, *scal;
    float *Mg, *uvp, *tvp, *c0p, *zb;
    __nv_bfloat16 *WH, *WL, *ZA, *ZB;
    int *rowptr, *cnt, *bsum, *cols;
    cudaGetSymbolAddress((void**)&Th, d_Th);
    cudaGetSymbolAddress((void**)&z, d_z);
    cudaGetSymbolAddress((void**)&Xb, d_Xb);
    cudaGetSymbolAddress((void**)&vb, d_vb);
    cudaGetSymbolAddress((void**)&T1, d_T1);
    cudaGetSymbolAddress((void**)&Trf, d_Trf);
    cudaGetSymbolAddress((void**)&A1, d_A1);
    cudaGetSymbolAddress((void**)&A2, d_A2);
    cudaGetSymbolAddress((void**)&AUb, d_AUb);
    cudaGetSymbolAddress((void**)&ZA, d_ZA);
    cudaGetSymbolAddress((void**)&ZB, d_ZB);
    cudaGetSymbolAddress((void**)&WH, d_WH);
    cudaGetSymbolAddress((void**)&WL, d_WL);
    cudaGetSymbolAddress((void**)&Mg, d_M);
    cudaGetSymbolAddress((void**)&uvp, d_uvec);
    cudaGetSymbolAddress((void**)&tvp, d_tvec);
    cudaGetSymbolAddress((void**)&c0p, d_c0s);
    cudaGetSymbolAddress((void**)&zb, d_zbias);
    cudaGetSymbolAddress((void**)&dinvp, d_dinv);
    cudaGetSymbolAddress((void**)&wp, d_w);
    cudaGetSymbolAddress((void**)&scal, d_scal);
    cudaGetSymbolAddress((void**)&rowptr, d_rowptr);
    cudaGetSymbolAddress((void**)&cnt, d_cnt);
    cudaGetSymbolAddress((void**)&bsum, d_bsum);
    cudaGetSymbolAddress((void**)&cols, d_cols);

    static bool attr_done = false;
    if (!attr_done) {
        cudaFuncSetAttribute(gemm_tc<0>, cudaFuncAttributeMaxDynamicSharedMemorySize, GSMEM);
        cudaFuncSetAttribute(gemm_tc<1>, cudaFuncAttributeMaxDynamicSharedMemorySize, GSMEM);
        cudaFuncSetAttribute(gemm_tc<2>, cudaFuncAttributeMaxDynamicSharedMemorySize, GSMEM);
        cudaFuncSetAttribute(gemm_tc_b4, cudaFuncAttributeMaxDynamicSharedMemorySize, GSMEM);
        attr_done = true;
    }

    const int GBX = (N + 63) / 64;
    dim3 gs1(GBX, 2), gs2(GBX, 4), gb4(GBX, 8), gcl(GBX, 1);
    const int VB = (n4 + 255) / 256;
    const float Ninv = 1.0f / (float)N;

    gram_kernel<<<66, 256>>>(Wq, Wk, bq, bk, Mg, uvp, tvp, c0p, scal, zb);

    WPtrs wpt;
    wpt.p[0] = KopenW; wpt.p[1] = convW; wpt.p[2] = Mg; wpt.p[3] = Mg;
    for (int j = 0; j < 4; j++) {
        wpt.p[4 + j] = KR1W + (size_t)j * WSLOT;
        wpt.p[8 + j] = KR2W + (size_t)j * WSLOT;
        wpt.p[12 + j] = KRU0W + (size_t)j * WSLOT;
    }
    wpt.p[16] = KcloseW;
    wconv_kernel<<<dim3(16, 17), 256>>>(wpt, WH, WL);

    csr_kernel<<<NBLK, CGT>>>(EI, E, N, cnt, dinvp, bsum, rowptr, cols, wp);

    gemm_tc<1><<<gs1, 256, GSMEM>>>(T, WH, WL, Kopenb, Th, WH, WL, Kopenb, Th, N, NH,
                                    bnOg, bnOb, bnOm, bnOv);
    gemm_tc<2><<<gs1, 256, GSMEM>>>(Th, WH + 1 * WSLOT, WL + 1 * WSLOT, convb, z,
                                    WH + 1 * WSLOT, WL + 1 * WSLOT, convb, z, N, NH,
                                    bnAg, bnAb, bnAm, bnAv);
    gemm_tc<0><<<gs1, 256, GSMEM>>>(z, WH + 2 * WSLOT, WL + 2 * WSLOT, zb, vb,
                                    WH + 2 * WSLOT, WL + 2 * WSLOT, zb, vb, N, NH, 0, 0, 0, 0);
    gemm_tc_b4<<<gb4, 256, GSMEM>>>(Th, WH + 12 * WSLOT, WL + 12 * WSLOT, KRU0b, AUb, S, N);

    for (int jj = 0; jj < 4; jj++) {
        const float* T1in;
        if (jj == 0) {
            T1in = z;  // all acts slots identical -> uniform softmax -> T1 == z exactly
        } else {
            gemm_tc<0><<<gs1, 256, GSMEM>>>(Xb + (jj - 1) * S,
                                            WH + 2 * WSLOT, WL + 2 * WSLOT, zb, vb + jj * S,
                                            WH + 2 * WSLOT, WL + 2 * WSLOT, zb, vb + jj * S,
                                            N, NH, 0, 0, 0, 0);
            const float *da[4] = {z, z, z, z};
            const float *dv[4] = {vb, vb, vb, vb};
            for (int m = 0; m < jj; m++) {
                da[m + 1] = Xb + m * S;
                dv[m + 1] = vb + (m + 1) * S;
            }
            float* sl = scal + jj * SSTR;
            if (jj == 1) {
                attn_kernel<2><<<400, 256>>>(da[0], da[1], da[2], da[3], dv[0], dv[1], dv[2], dv[3],
                                             uvp, tvp, c0p, mha, sl, N);
                combine4<2><<<VB, 256>>>(da[0], da[1], da[2], da[3], sl, Ninv, T1, n4);
            } else if (jj == 2) {
                attn_kernel<3><<<400, 256>>>(da[0], da[1], da[2], da[3], dv[0], dv[1], dv[2], dv[3],
                                             uvp, tvp, c0p, mha, sl, N);
                combine4<3><<<VB, 256>>>(da[0], da[1], da[2], da[3], sl, Ninv, T1, n4);
            } else {
                attn_kernel<4><<<400, 256>>>(da[0], da[1], da[2], da[3], dv[0], dv[1], dv[2], dv[3],
                                             uvp, tvp, c0p, mha, sl, N);
                combine4<4><<<VB, 256>>>(da[0], da[1], da[2], da[3], sl, Ninv, T1, n4);
            }
            T1in = T1;
        }

        gemm_tc<0><<<gs2, 256, GSMEM>>>(T1in,
                                        WH + (4 + jj) * WSLOT, WL + (4 + jj) * WSLOT,
                                        KR1b + jj * NH, A1,
                                        WH + (8 + jj) * WSLOT, WL + (8 + jj) * WSLOT,
                                        KR2b + jj * NH, A2, N, NH, 0, 0, 0, 0);

        cheb_kernel<<<NBLK, CGT>>>(T1in, A1, A2, AUb + jj * S, bng + jj * NH, bnbp + jj * NH,
                                   bnm + jj * NH, bnv + jj * NH, rowptr, cols, wp,
                                   Kappa + jj * NH, Xb + jj * S, Trf, ZA, ZB, N);
    }
    gemm_tc<0><<<gcl, 256, GSMEM>>>(Xb + 3 * S, WH + 16 * WSLOT, WL + 16 * WSLOT, Kcloseb,
                                    (float*)d_out, WH + 16 * WSLOT, WL + 16 * WSLOT, Kcloseb,
                                    (float*)d_out, N, 40, 0, 0, 0, 0);
}